// round 3
// baseline (speedup 1.0000x reference)
#include <cuda_runtime.h>

#define B_ 8
#define C1_ 256
#define C2_ 512
#define H1_ 64
#define W1_ 64
#define N1_ 4096
#define H2_ 32
#define W2_ 32
#define N2_ 1024
#define CR_ 32

// ---------------- scratch (device globals; no allocations) ----------------
__device__ float g_q[B_*CR_*N1_];     // [b][c][m]
__device__ float g_k[B_*CR_*N2_];     // [b][c][n]
__device__ float g_v[B_*C1_*N2_];     // [b][c][n]
__device__ float g_logit[B_*N1_];
__device__ float g_cf[B_*N1_];
__device__ float g_y[B_*C1_*9];
__device__ float g_cw[B_*C1_];

// ---------------- fast exp on FMA pipe (avoids MUFU bottleneck) -----------
__device__ __forceinline__ float fexp(float x) {
    x = fmaxf(x, -80.f);
    float t = x * 1.4426950408889634f;
    float z = t + 12582912.f;                 // round-to-nearest-int trick
    int   i = __float_as_int(z) - 0x4B400000;
    float f = t - (z - 12582912.f);           // in [-0.5, 0.5]
    float y = f * 0.6931471805599453f;
    float p = 1.f/720.f;
    p = fmaf(p, y, 1.f/120.f);
    p = fmaf(p, y, 1.f/24.f);
    p = fmaf(p, y, 1.f/6.f);
    p = fmaf(p, y, 0.5f);
    p = fmaf(p, y, 1.f);
    p = fmaf(p, y, 1.f);
    return p * __int_as_float((i + 127) << 23);
}

// ---------------- generic direct conv3x3, SAME pad ------------------------
// block: 256 thr; tile 16x16 spatial, 32 couts; per-thread 4sp x 8co regs
__global__ __launch_bounds__(256) void conv3x3_k(
    const float* __restrict__ in, const float* __restrict__ wgt, float* __restrict__ out,
    int Cin, int Cout, int H, int W, int tilesW)
{
    __shared__ float in_s[8*324];    // [ci][18][18]
    __shared__ float w_s[32*72];     // [co][ci][9]
    int t  = threadIdx.x;
    int b  = blockIdx.z;
    int co_base = blockIdx.y * 32;
    int tw = blockIdx.x % tilesW, th = blockIdx.x / tilesW;
    int h0 = th*16, w0 = tw*16;
    int sp = t & 63, cs = t >> 6;           // 64 spatial slots x 4 co slots
    int hh = sp >> 2, ww = (sp & 3) << 2;

    float acc[8][4];
    #pragma unroll
    for (int j = 0; j < 8; j++)
        #pragma unroll
        for (int s = 0; s < 4; s++) acc[j][s] = 0.f;

    for (int ci0 = 0; ci0 < Cin; ci0 += 8) {
        for (int idx = t; idx < 8*324; idx += 256) {
            int ci = idx / 324; int rem = idx - ci*324;
            int r = rem / 18;   int c = rem - r*18;
            int gh = h0 + r - 1, gw = w0 + c - 1;
            float v = 0.f;
            if (gh >= 0 && gh < H && gw >= 0 && gw < W)
                v = in[((b*Cin + ci0+ci)*H + gh)*W + gw];
            in_s[idx] = v;
        }
        for (int idx = t; idx < 32*72; idx += 256) {
            int co = idx / 72; int rem = idx - co*72;
            int ci = rem / 9;  int k = rem - ci*9;
            w_s[idx] = wgt[((co_base+co)*Cin + ci0+ci)*9 + k];
        }
        __syncthreads();
        #pragma unroll 2
        for (int ci = 0; ci < 8; ++ci) {
            float xr[3][6];
            #pragma unroll
            for (int r = 0; r < 3; r++)
                #pragma unroll
                for (int c = 0; c < 6; c++)
                    xr[r][c] = in_s[ci*324 + (hh+r)*18 + ww + c];
            #pragma unroll
            for (int j = 0; j < 8; j++) {
                const float* wp = w_s + (cs*8+j)*72 + ci*9;
                #pragma unroll
                for (int dy = 0; dy < 3; dy++)
                    #pragma unroll
                    for (int dx = 0; dx < 3; dx++) {
                        float wv = wp[dy*3+dx];
                        #pragma unroll
                        for (int s = 0; s < 4; s++)
                            acc[j][s] = fmaf(xr[dy][dx+s], wv, acc[j][s]);
                    }
            }
        }
        __syncthreads();
    }
    #pragma unroll
    for (int j = 0; j < 8; j++) {
        int co = co_base + cs*8 + j;
        float* op = out + ((b*Cout + co)*H + (h0+hh))*W + w0 + ww;
        #pragma unroll
        for (int s = 0; s < 4; s++) op[s] = acc[j][s];
    }
}

// ---------------- channel branch: cf logits (1x1 conv) --------------------
__global__ __launch_bounds__(256) void cf_logit_k(const float* __restrict__ x1,
                                                  const float* __restrict__ wc)
{
    __shared__ float wc_s[C1_];
    int t = threadIdx.x, b = blockIdx.y;
    wc_s[t] = wc[t];
    __syncthreads();
    int n = blockIdx.x*256 + t;
    float a = 0.f;
    const float* xp = x1 + b*C1_*N1_ + n;
    #pragma unroll 4
    for (int c = 0; c < C1_; c++) a = fmaf(wc_s[c], xp[c*N1_], a);
    g_logit[b*N1_ + n] = a;
}

// ---------------- cf softmax over N1 (per b) -------------------------------
__global__ __launch_bounds__(1024) void cf_softmax_k()
{
    int b = blockIdx.x, t = threadIdx.x;
    __shared__ float red[32];
    float v[4];
    #pragma unroll
    for (int i = 0; i < 4; i++) v[i] = g_logit[b*N1_ + t + 1024*i];
    float mx = fmaxf(fmaxf(v[0],v[1]), fmaxf(v[2],v[3]));
    #pragma unroll
    for (int o = 16; o; o >>= 1) mx = fmaxf(mx, __shfl_xor_sync(~0u, mx, o));
    if ((t&31) == 0) red[t>>5] = mx;
    __syncthreads();
    if (t < 32) {
        float m2 = red[t];
        #pragma unroll
        for (int o = 16; o; o >>= 1) m2 = fmaxf(m2, __shfl_xor_sync(~0u, m2, o));
        red[t] = m2;
    }
    __syncthreads();
    mx = red[0];
    __syncthreads();
    float e[4]; float s = 0.f;
    #pragma unroll
    for (int i = 0; i < 4; i++) { e[i] = fexp(v[i]-mx); s += e[i]; }
    #pragma unroll
    for (int o = 16; o; o >>= 1) s += __shfl_xor_sync(~0u, s, o);
    if ((t&31) == 0) red[t>>5] = s;
    __syncthreads();
    if (t < 32) {
        float s2 = red[t];
        #pragma unroll
        for (int o = 16; o; o >>= 1) s2 += __shfl_xor_sync(~0u, s2, o);
        red[t] = s2;
    }
    __syncthreads();
    float inv = 1.f / red[0];
    #pragma unroll
    for (int i = 0; i < 4; i++) g_cf[b*N1_ + t + 1024*i] = e[i]*inv;
}

// ---------------- y[b,i,dy,dx] = sum_p x1[b,i,p]*cf_pad[b, p-(dy-1,dx-1)] --
// (commutes the 38.7 GF chf conv with the cf contraction -> 0.15 GF)
__global__ __launch_bounds__(256) void y_k(const float* __restrict__ x1)
{
    __shared__ float cf_s[N1_];
    __shared__ float part[8][9];
    int i = blockIdx.x, b = blockIdx.y, t = threadIdx.x;
    for (int idx = t; idx < N1_; idx += 256) cf_s[idx] = g_cf[b*N1_ + idx];
    __syncthreads();
    float a[9];
    #pragma unroll
    for (int k = 0; k < 9; k++) a[k] = 0.f;
    const float* xp = x1 + (b*C1_ + i)*N1_;
    for (int p = t; p < N1_; p += 256) {
        float xv = xp[p];
        int ph = p >> 6, pw = p & 63;
        #pragma unroll
        for (int dy = 0; dy < 3; dy++) {
            int qh = ph + 1 - dy;
            if ((unsigned)qh < 64u) {
                #pragma unroll
                for (int dx = 0; dx < 3; dx++) {
                    int qw = pw + 1 - dx;
                    if ((unsigned)qw < 64u)
                        a[dy*3+dx] = fmaf(xv, cf_s[(qh<<6)+qw], a[dy*3+dx]);
                }
            }
        }
    }
    #pragma unroll
    for (int k = 0; k < 9; k++) {
        float s = a[k];
        #pragma unroll
        for (int o = 16; o; o >>= 1) s += __shfl_xor_sync(~0u, s, o);
        if ((t&31) == 0) part[t>>5][k] = s;
    }
    __syncthreads();
    if (t < 9) {
        float s = 0.f;
        #pragma unroll
        for (int w = 0; w < 8; w++) s += part[w][t];
        g_y[(b*C1_+i)*9 + t] = s;
    }
}

// ---------------- pool = wch*y ; t = wt1*pool ; LN ; relu ; cw = wt2*t -----
__global__ __launch_bounds__(256) void chtail_k(
    const float* __restrict__ wch, const float* __restrict__ wt1,
    const float* __restrict__ bt1, const float* __restrict__ lng,
    const float* __restrict__ lnb, const float* __restrict__ wt2,
    const float* __restrict__ bt2)
{
    __shared__ float y_s[C1_*9];
    __shared__ float pool_s[C1_];
    __shared__ float t_s[CR_];
    int b = blockIdx.x, t = threadIdx.x;
    for (int idx = t; idx < C1_*9; idx += 256) y_s[idx] = g_y[b*C1_*9 + idx];
    __syncthreads();
    {
        float a = 0.f;
        const float* wp = wch + t*(C1_*9);
        #pragma unroll 4
        for (int idx = 0; idx < C1_*9; idx++) a = fmaf(wp[idx], y_s[idx], a);
        pool_s[t] = a;
    }
    __syncthreads();
    if (t < CR_) {
        float tv = bt1[t];
        const float* wp = wt1 + t*C1_;
        #pragma unroll 4
        for (int c = 0; c < C1_; c++) tv = fmaf(wp[c], pool_s[c], tv);
        float s1 = tv;
        #pragma unroll
        for (int o = 16; o; o >>= 1) s1 += __shfl_xor_sync(~0u, s1, o);
        float mu = s1 * (1.f/32.f);
        float d  = tv - mu;
        float s2 = d*d;
        #pragma unroll
        for (int o = 16; o; o >>= 1) s2 += __shfl_xor_sync(~0u, s2, o);
        float var = s2 * (1.f/32.f);
        float val = d * rsqrtf(var + 1e-5f) * lng[t] + lnb[t];
        t_s[t] = fmaxf(val, 0.f);
    }
    __syncthreads();
    {
        float a = bt2[t];
        const float* wp = wt2 + t*CR_;
        #pragma unroll
        for (int j = 0; j < CR_; j++) a = fmaf(wp[j], t_s[j], a);
        g_cw[b*C1_ + t] = a;
    }
}

// ---------------- fused attention: S = K^T Q, softmax_n, O = V P; epilogue -
// one CTA = (b, 32 queries); scores kept in smem (32 x 1025), 169 KB dynamic
#define SPITCH 1025
#define ATTN_SMEM ((32*SPITCH + 32*33 + 256*33) * 4)

__global__ __launch_bounds__(256, 1) void attn_kernel(const float* __restrict__ x1,
                                                      float* __restrict__ out)
{
    extern __shared__ float sm[];
    float* s_P  = sm;                  // [32][1025] scores -> unnorm probs
    float* s_q  = sm + 32*SPITCH;      // [32][33] q tile; later inv[32]
    float* s_kv = s_q + 32*33;         // k chunk [32][257] / v chunk [256][33]
    int t  = threadIdx.x;
    int b  = blockIdx.y;
    int m0 = blockIdx.x * 32;

    for (int idx = t; idx < 1024; idx += 256) {
        int c = idx >> 5, m = idx & 31;
        s_q[c*33 + m] = g_q[(b*CR_ + c)*N1_ + m0 + m];
    }
    __syncthreads();

    // ---- phase 1: S[m][n] = sum_c q[c][m]*k[c][n]
    {
        int tn = t & 31, tmg = t >> 5;
        for (int nb = 0; nb < N2_; nb += 256) {
            for (int idx = t; idx < 32*256; idx += 256) {
                int c = idx >> 8, n = idx & 255;
                s_kv[c*257 + n] = g_k[(b*CR_ + c)*N2_ + nb + n];
            }
            __syncthreads();
            float a[4][8];
            #pragma unroll
            for (int im = 0; im < 4; im++)
                #pragma unroll
                for (int jn = 0; jn < 8; jn++) a[im][jn] = 0.f;
            #pragma unroll 4
            for (int c = 0; c < 32; c++) {
                float qv[4];
                #pragma unroll
                for (int im = 0; im < 4; im++) qv[im] = s_q[c*33 + tmg*4 + im];
                #pragma unroll
                for (int jn = 0; jn < 8; jn++) {
                    float kv = s_kv[c*257 + tn + 32*jn];
                    #pragma unroll
                    for (int im = 0; im < 4; im++)
                        a[im][jn] = fmaf(qv[im], kv, a[im][jn]);
                }
            }
            #pragma unroll
            for (int im = 0; im < 4; im++)
                #pragma unroll
                for (int jn = 0; jn < 8; jn++)
                    s_P[(tmg*4+im)*SPITCH + nb + tn + 32*jn] = a[im][jn];
            __syncthreads();
        }
    }

    // ---- phase 2: per-row softmax over n (max-sub; store unnorm exp; inv later)
    {
        int m = t >> 3, g = t & 7;
        float* row = s_P + m*SPITCH;
        float mx = -3e38f;
        for (int i = g; i < 1024; i += 8) mx = fmaxf(mx, row[i]);
        #pragma unroll
        for (int o = 4; o; o >>= 1) mx = fmaxf(mx, __shfl_xor_sync(~0u, mx, o));
        float sum = 0.f;
        for (int i = g; i < 1024; i += 8) {
            float e = fexp(row[i] - mx);
            row[i] = e; sum += e;
        }
        #pragma unroll
        for (int o = 4; o; o >>= 1) sum += __shfl_xor_sync(~0u, sum, o);
        if (g == 0) s_q[m] = 1.f / sum;
    }
    __syncthreads();

    // ---- phase 3: O[c][m] = sum_n v[c][n]*P[m][n]; fused epilogue
    {
        int tc = t & 31, tm4 = t >> 5;
        float acc[8][4];
        #pragma unroll
        for (int jc = 0; jc < 8; jc++)
            #pragma unroll
            for (int im = 0; im < 4; im++) acc[jc][im] = 0.f;
        for (int nb = 0; nb < N2_; nb += 32) {
            for (int idx = t; idx < 256*32; idx += 256) {
                int c = idx >> 5, n = idx & 31;
                s_kv[c*33 + n] = g_v[(b*C1_ + c)*N2_ + nb + n];
            }
            __syncthreads();
            #pragma unroll 4
            for (int n = 0; n < 32; n++) {
                float pv[4];
                #pragma unroll
                for (int im = 0; im < 4; im++)
                    pv[im] = s_P[(tm4*4+im)*SPITCH + nb + n];
                #pragma unroll
                for (int jc = 0; jc < 8; jc++) {
                    float vv = s_kv[(tc + 32*jc)*33 + n];
                    #pragma unroll
                    for (int im = 0; im < 4; im++)
                        acc[jc][im] = fmaf(vv, pv[im], acc[jc][im]);
                }
            }
            __syncthreads();
        }
        float inv[4];
        #pragma unroll
        for (int im = 0; im < 4; im++) inv[im] = s_q[tm4*4 + im];
        #pragma unroll
        for (int jc = 0; jc < 8; jc++) {
            int c = tc + 32*jc;
            float cw = 1.f + g_cw[b*C1_ + c];
            #pragma unroll
            for (int im = 0; im < 4; im++) {
                int m   = m0 + tm4*4 + im;
                int off = (b*C1_ + c)*N1_ + m;
                out[off] = fmaf(acc[jc][im], inv[im], x1[off]*cw);
            }
        }
    }
}

// ---------------------------------------------------------------------------
extern "C" void kernel_launch(void* const* d_in, const int* in_sizes, int n_in,
                              void* d_out, int out_size)
{
    (void)in_sizes; (void)n_in; (void)out_size;
    const float* x1  = (const float*)d_in[0];
    const float* x2  = (const float*)d_in[1];
    const float* wq  = (const float*)d_in[2];
    const float* wk  = (const float*)d_in[3];
    const float* wv  = (const float*)d_in[4];
    const float* wc  = (const float*)d_in[5];
    const float* wch = (const float*)d_in[6];
    const float* wt1 = (const float*)d_in[7];
    const float* bt1 = (const float*)d_in[8];
    const float* lng = (const float*)d_in[9];
    const float* lnb = (const float*)d_in[10];
    const float* wt2 = (const float*)d_in[11];
    const float* bt2 = (const float*)d_in[12];
    float* out = (float*)d_out;

    float *pq, *pk, *pv;
    cudaGetSymbolAddress((void**)&pq, g_q);
    cudaGetSymbolAddress((void**)&pk, g_k);
    cudaGetSymbolAddress((void**)&pv, g_v);

    // convs (independent)
    conv3x3_k<<<dim3(16, 1, B_), 256>>>(x1, wq, pq, C1_, CR_, H1_, W1_, 4);
    conv3x3_k<<<dim3(4,  1, B_), 256>>>(x2, wk, pk, C2_, CR_, H2_, W2_, 2);
    conv3x3_k<<<dim3(4,  8, B_), 256>>>(x2, wv, pv, C2_, C1_, H2_, W2_, 2);

    // channel branch
    cf_logit_k<<<dim3(N1_/256, B_), 256>>>(x1, wc);
    cf_softmax_k<<<B_, 1024>>>();
    y_k<<<dim3(C1_, B_), 256>>>(x1);
    chtail_k<<<B_, 256>>>(wch, wt1, bt1, lng, lnb, wt2, bt2);

    // fused attention + final epilogue
    cudaFuncSetAttribute(attn_kernel, cudaFuncAttributeMaxDynamicSharedMemorySize,
                         ATTN_SMEM);
    attn_kernel<<<dim3(N1_/32, B_), 256, ATTN_SMEM>>>(x1, out);
}

// round 5
// speedup vs baseline: 1.1020x; 1.1020x over previous
#include <cuda_runtime.h>

#define B_ 8
#define C1_ 256
#define C2_ 512
#define H1_ 64
#define W1_ 64
#define N1_ 4096
#define H2_ 32
#define W2_ 32
#define N2_ 1024
#define CR_ 32

// ---------------- scratch (device globals; no allocations) ----------------
__device__ float g_q[B_*CR_*N1_];       // [b][c][m]
__device__ float g_k[B_*CR_*N2_];       // [b][c][n]
__device__ float g_kpart[8*B_*CR_*N2_]; // 8 ci-split partials for conv_k
__device__ float g_v[B_*C1_*N2_];       // [b][c][n]
__device__ float g_S[B_*N1_*N2_];       // scores [b][m][n]; overwritten by P
__device__ float g_logit[B_*N1_];
__device__ float g_cf[B_*N1_];
__device__ float g_y[B_*C1_*9];
__device__ float g_cw[B_*C1_];

// ---------------- f32x2 helpers (packed FFMA2 on the FMA pipe) ------------
__device__ __forceinline__ unsigned long long pack2(float x, float y) {
    unsigned long long r;
    asm("mov.b64 %0, {%1, %2};" : "=l"(r) : "f"(x), "f"(y));
    return r;
}
__device__ __forceinline__ void unpack2(unsigned long long v, float& x, float& y) {
    asm("mov.b64 {%0, %1}, %2;" : "=f"(x), "=f"(y) : "l"(v));
}
__device__ __forceinline__ void ffma2(unsigned long long& d,
                                      unsigned long long a, unsigned long long b) {
    asm("fma.rn.f32x2 %0, %1, %2, %0;" : "+l"(d) : "l"(a), "l"(b));
}
__device__ __forceinline__ unsigned long long lds64(unsigned addr) {
    unsigned long long r;
    asm volatile("ld.shared.b64 %0, [%1];" : "=l"(r) : "r"(addr));
    return r;
}

// ---------------- fast exp on FMA pipe ------------------------------------
__device__ __forceinline__ float fexp(float x) {
    x = fmaxf(x, -80.f);
    float t = x * 1.4426950408889634f;
    float z = t + 12582912.f;
    int   i = __float_as_int(z) - 0x4B400000;
    float f = t - (z - 12582912.f);
    float y = f * 0.6931471805599453f;
    float p = 1.f/720.f;
    p = fmaf(p, y, 1.f/120.f);
    p = fmaf(p, y, 1.f/24.f);
    p = fmaf(p, y, 1.f/6.f);
    p = fmaf(p, y, 0.5f);
    p = fmaf(p, y, 1.f);
    p = fmaf(p, y, 1.f);
    return p * __int_as_float((i + 127) << 23);
}

// ---------------- direct conv3x3, SAME pad, f32x2 co-pair packing ---------
// 16x16 spatial tile, 32 couts, optional ci-split (slab partial outputs)
__global__ __launch_bounds__(256) void conv3x3_k(
    const float* __restrict__ in, const float* __restrict__ wgt, float* __restrict__ out,
    int Cin_total, int ci_count, int Cout, int H, int W, int tilesW, int co_groups,
    int slab_stride)
{
    __shared__ float in_s[8*324];    // [ci][18][18]
    __shared__ float w2_s[32*72];    // co-paired: ((co>>1)*72 + ci*9+k)*2 + (co&1)
    int t  = threadIdx.x;
    int b  = blockIdx.z;
    int co_base = (blockIdx.y % co_groups) * 32;
    int ci_g    = blockIdx.y / co_groups;
    int cib     = ci_g * ci_count;
    int tw = blockIdx.x % tilesW, th = blockIdx.x / tilesW;
    int h0 = th*16, w0 = tw*16;
    int sp = t & 63, cs = t >> 6;
    int hh = sp >> 2, ww = (sp & 3) << 2;
    unsigned wbase = (unsigned)__cvta_generic_to_shared(w2_s);

    unsigned long long acc2[4][4];   // [co-pair][spatial]
    #pragma unroll
    for (int jp = 0; jp < 4; jp++)
        #pragma unroll
        for (int s = 0; s < 4; s++) acc2[jp][s] = 0ull;

    for (int ci0 = 0; ci0 < ci_count; ci0 += 8) {
        for (int idx = t; idx < 8*324; idx += 256) {
            int ci = idx / 324; int rem = idx - ci*324;
            int r = rem / 18;   int c = rem - r*18;
            int gh = h0 + r - 1, gw = w0 + c - 1;
            float v = 0.f;
            if (gh >= 0 && gh < H && gw >= 0 && gw < W)
                v = in[((size_t)(b*Cin_total + cib+ci0+ci)*H + gh)*W + gw];
            in_s[idx] = v;
        }
        for (int idx = t; idx < 32*72; idx += 256) {
            int co = idx / 72; int r = idx - co*72;
            int cil = r / 9;   int k = r - cil*9;
            w2_s[((co>>1)*72 + r)*2 + (co&1)] =
                wgt[((size_t)(co_base+co)*Cin_total + cib+ci0+cil)*9 + k];
        }
        __syncthreads();
        #pragma unroll 2
        for (int ci = 0; ci < 8; ++ci) {
            float xr[3][6];
            #pragma unroll
            for (int r = 0; r < 3; r++)
                #pragma unroll
                for (int c = 0; c < 6; c++)
                    xr[r][c] = in_s[ci*324 + (hh+r)*18 + ww + c];
            #pragma unroll
            for (int dy = 0; dy < 3; dy++)
                #pragma unroll
                for (int dx = 0; dx < 3; dx++) {
                    unsigned long long xp[4];
                    #pragma unroll
                    for (int s = 0; s < 4; s++)
                        xp[s] = pack2(xr[dy][dx+s], xr[dy][dx+s]);
                    #pragma unroll
                    for (int jp = 0; jp < 4; jp++) {
                        unsigned long long w2 =
                            lds64(wbase + (unsigned)(((cs*4+jp)*72 + ci*9 + dy*3+dx) << 3));
                        #pragma unroll
                        for (int s = 0; s < 4; s++) ffma2(acc2[jp][s], w2, xp[s]);
                    }
                }
        }
        __syncthreads();
    }
    float* op = out + (size_t)ci_g * slab_stride;
    #pragma unroll
    for (int jp = 0; jp < 4; jp++) {
        int co = co_base + cs*8 + jp*2;
        float e[4], o[4];
        #pragma unroll
        for (int s = 0; s < 4; s++) unpack2(acc2[jp][s], e[s], o[s]);
        *(float4*)(op + ((size_t)(b*Cout + co)*H + (h0+hh))*W + w0 + ww)
            = make_float4(e[0], e[1], e[2], e[3]);
        *(float4*)(op + ((size_t)(b*Cout + co + 1)*H + (h0+hh))*W + w0 + ww)
            = make_float4(o[0], o[1], o[2], o[3]);
    }
}

// ---------------- reduce 8 ci-partials for conv_k -------------------------
__global__ __launch_bounds__(256) void reduce_k8()
{
    int i = blockIdx.x*256 + threadIdx.x;      // float4 index, 65536 total
    const float4* p = (const float4*)g_kpart;
    float4 s = p[i];
    #pragma unroll
    for (int g = 1; g < 8; g++) {
        float4 a = p[g*65536 + i];
        s.x += a.x; s.y += a.y; s.z += a.z; s.w += a.w;
    }
    ((float4*)g_k)[i] = s;
}

// ---------------- S[m][n] = sum_c q[c][m] k[c][n]  (128x128 tiles) --------
__global__ __launch_bounds__(256, 2) void s_gemm_k()
{
    __shared__ float q_s[32*128];
    __shared__ float k_s[32*128];
    int t = threadIdx.x, b = blockIdx.z;
    int m0 = blockIdx.x*128, n0 = blockIdx.y*128;
    for (int i = t; i < 1024; i += 256) {
        int c = i >> 5, j = i & 31;
        ((float4*)q_s)[i] = *(const float4*)(g_q + ((size_t)(b*CR_ + c))*N1_ + m0 + 4*j);
        ((float4*)k_s)[i] = *(const float4*)(g_k + ((size_t)(b*CR_ + c))*N2_ + n0 + 4*j);
    }
    __syncthreads();
    int tn = t & 15, tm = t >> 4;
    unsigned kb = (unsigned)__cvta_generic_to_shared(k_s);
    unsigned long long acc2[8][4];
    #pragma unroll
    for (int im = 0; im < 8; im++)
        #pragma unroll
        for (int jn = 0; jn < 4; jn++) acc2[im][jn] = 0ull;
    #pragma unroll 4
    for (int c = 0; c < 32; c++) {
        unsigned long long ad[8], bd[4];
        #pragma unroll
        for (int im = 0; im < 8; im++) {
            float qv = q_s[c*128 + tm*8 + im];
            ad[im] = pack2(qv, qv);
        }
        #pragma unroll
        for (int jn = 0; jn < 4; jn++)
            bd[jn] = lds64(kb + (unsigned)((c*128 + tn*2 + 32*jn) << 2));
        #pragma unroll
        for (int im = 0; im < 8; im++)
            #pragma unroll
            for (int jn = 0; jn < 4; jn++)
                ffma2(acc2[im][jn], ad[im], bd[jn]);
    }
    #pragma unroll
    for (int im = 0; im < 8; im++) {
        float* row = g_S + ((size_t)(b*N1_) + m0 + tm*8 + im)*N2_ + n0;
        #pragma unroll
        for (int jn = 0; jn < 4; jn++) {
            float x, y; unpack2(acc2[im][jn], x, y);
            *(float2*)(row + tn*2 + 32*jn) = make_float2(x, y);
        }
    }
}

// ---------------- row softmax over n; normalize in place ------------------
__global__ __launch_bounds__(256) void softmax_k()
{
    int b = blockIdx.y;
    int m = blockIdx.x*8 + (threadIdx.x >> 5);
    int lane = threadIdx.x & 31;
    float4* row = (float4*)(g_S + ((size_t)(b*N1_) + m)*N2_);
    float4 v[8];
    #pragma unroll
    for (int j = 0; j < 8; j++) v[j] = row[lane + 32*j];
    float mx = -3e38f;
    #pragma unroll
    for (int j = 0; j < 8; j++)
        mx = fmaxf(mx, fmaxf(fmaxf(v[j].x, v[j].y), fmaxf(v[j].z, v[j].w)));
    #pragma unroll
    for (int o = 16; o; o >>= 1) mx = fmaxf(mx, __shfl_xor_sync(~0u, mx, o));
    float s = 0.f;
    #pragma unroll
    for (int j = 0; j < 8; j++) {
        v[j].x = fexp(v[j].x - mx); v[j].y = fexp(v[j].y - mx);
        v[j].z = fexp(v[j].z - mx); v[j].w = fexp(v[j].w - mx);
        s += v[j].x + v[j].y + v[j].z + v[j].w;
    }
    #pragma unroll
    for (int o = 16; o; o >>= 1) s += __shfl_xor_sync(~0u, s, o);
    float inv = 1.f / s;
    #pragma unroll
    for (int j = 0; j < 8; j++) {
        v[j].x *= inv; v[j].y *= inv; v[j].z *= inv; v[j].w *= inv;
        row[lane + 32*j] = v[j];
    }
}

// ---------------- O[c][m] = sum_n V[c][n] P[m][n]; fused epilogue ---------
#define OP_ 134
__global__ __launch_bounds__(256, 2) void o_gemm_k(const float* __restrict__ x1,
                                                   float* __restrict__ out)
{
    __shared__ float a_s[16*OP_];    // [n][c]
    __shared__ float b_s[16*OP_];    // [n][m]
    int t = threadIdx.x, b = blockIdx.z;
    int m0 = blockIdx.x*128, c0 = blockIdx.y*128;
    int tmq = t & 15, tcq = t >> 4;
    int rr = t >> 1, nh = (t & 1)*8;
    const float* vsrc = g_v + ((size_t)(b*C1_ + c0 + rr))*N2_ + nh;
    const float* psrc = g_S + ((size_t)(b*N1_ + m0 + rr))*N2_ + nh;
    unsigned bb = (unsigned)__cvta_generic_to_shared(b_s);
    unsigned long long acc2[8][4];
    #pragma unroll
    for (int i = 0; i < 8; i++)
        #pragma unroll
        for (int j = 0; j < 4; j++) acc2[i][j] = 0ull;

    for (int nb = 0; nb < N2_; nb += 16) {
        float4 a0 = *(const float4*)(vsrc + nb);
        float4 a1 = *(const float4*)(vsrc + nb + 4);
        float4 p0 = *(const float4*)(psrc + nb);
        float4 p1 = *(const float4*)(psrc + nb + 4);
        __syncthreads();                 // prior compute done before overwrite
        a_s[(nh+0)*OP_ + rr] = a0.x; a_s[(nh+1)*OP_ + rr] = a0.y;
        a_s[(nh+2)*OP_ + rr] = a0.z; a_s[(nh+3)*OP_ + rr] = a0.w;
        a_s[(nh+4)*OP_ + rr] = a1.x; a_s[(nh+5)*OP_ + rr] = a1.y;
        a_s[(nh+6)*OP_ + rr] = a1.z; a_s[(nh+7)*OP_ + rr] = a1.w;
        b_s[(nh+0)*OP_ + rr] = p0.x; b_s[(nh+1)*OP_ + rr] = p0.y;
        b_s[(nh+2)*OP_ + rr] = p0.z; b_s[(nh+3)*OP_ + rr] = p0.w;
        b_s[(nh+4)*OP_ + rr] = p1.x; b_s[(nh+5)*OP_ + rr] = p1.y;
        b_s[(nh+6)*OP_ + rr] = p1.z; b_s[(nh+7)*OP_ + rr] = p1.w;
        __syncthreads();
        #pragma unroll 4
        for (int n = 0; n < 16; n++) {
            unsigned long long ad[8], bd[4];
            #pragma unroll
            for (int i = 0; i < 8; i++) {
                float av = a_s[n*OP_ + tcq*8 + i];
                ad[i] = pack2(av, av);
            }
            #pragma unroll
            for (int j = 0; j < 4; j++)
                bd[j] = lds64(bb + (unsigned)((n*OP_ + tmq*2 + 32*j) << 2));
            #pragma unroll
            for (int i = 0; i < 8; i++)
                #pragma unroll
                for (int j = 0; j < 4; j++)
                    ffma2(acc2[i][j], ad[i], bd[j]);
        }
    }
    float wm[8];
    #pragma unroll
    for (int i = 0; i < 8; i++) wm[i] = 1.f + g_cw[b*C1_ + c0 + tcq*8 + i];
    #pragma unroll
    for (int i = 0; i < 8; i++)
        #pragma unroll
        for (int j = 0; j < 4; j++) {
            float x, y; unpack2(acc2[i][j], x, y);
            size_t off = ((size_t)(b*C1_ + c0 + tcq*8 + i))*N1_ + m0 + tmq*2 + 32*j;
            float2 xv = *(const float2*)(x1 + off);
            *(float2*)(out + off) = make_float2(fmaf(xv.x, wm[i], x),
                                                fmaf(xv.y, wm[i], y));
        }
}

// ---------------- channel branch: cf logits (1x1 conv), high MLP ----------
__global__ __launch_bounds__(256) void cf_logit_k(const float* __restrict__ x1,
                                                  const float* __restrict__ wc)
{
    __shared__ float wc_s[C1_];
    int t = threadIdx.x, b = blockIdx.y;
    wc_s[t] = wc[t];
    __syncthreads();
    int n = blockIdx.x*256 + t;
    const float* xp = x1 + (size_t)b*C1_*N1_ + n;
    float s0 = 0.f, s1 = 0.f, s2 = 0.f, s3 = 0.f;
    #pragma unroll 4
    for (int c = 0; c < C1_; c += 4) {
        s0 = fmaf(wc_s[c+0], __ldg(xp + (size_t)(c+0)*N1_), s0);
        s1 = fmaf(wc_s[c+1], __ldg(xp + (size_t)(c+1)*N1_), s1);
        s2 = fmaf(wc_s[c+2], __ldg(xp + (size_t)(c+2)*N1_), s2);
        s3 = fmaf(wc_s[c+3], __ldg(xp + (size_t)(c+3)*N1_), s3);
    }
    g_logit[b*N1_ + n] = (s0 + s1) + (s2 + s3);
}

// ---------------- cf softmax over N1 (per b) -------------------------------
__global__ __launch_bounds__(1024) void cf_softmax_k()
{
    int b = blockIdx.x, t = threadIdx.x;
    __shared__ float red[32];
    float v[4];
    #pragma unroll
    for (int i = 0; i < 4; i++) v[i] = g_logit[b*N1_ + t + 1024*i];
    float mx = fmaxf(fmaxf(v[0],v[1]), fmaxf(v[2],v[3]));
    #pragma unroll
    for (int o = 16; o; o >>= 1) mx = fmaxf(mx, __shfl_xor_sync(~0u, mx, o));
    if ((t&31) == 0) red[t>>5] = mx;
    __syncthreads();
    if (t < 32) {
        float m2 = red[t];
        #pragma unroll
        for (int o = 16; o; o >>= 1) m2 = fmaxf(m2, __shfl_xor_sync(~0u, m2, o));
        red[t] = m2;
    }
    __syncthreads();
    mx = red[0];
    __syncthreads();
    float e[4]; float s = 0.f;
    #pragma unroll
    for (int i = 0; i < 4; i++) { e[i] = fexp(v[i]-mx); s += e[i]; }
    #pragma unroll
    for (int o = 16; o; o >>= 1) s += __shfl_xor_sync(~0u, s, o);
    if ((t&31) == 0) red[t>>5] = s;
    __syncthreads();
    if (t < 32) {
        float s2 = red[t];
        #pragma unroll
        for (int o = 16; o; o >>= 1) s2 += __shfl_xor_sync(~0u, s2, o);
        red[t] = s2;
    }
    __syncthreads();
    float inv = 1.f / red[0];
    #pragma unroll
    for (int i = 0; i < 4; i++) g_cf[b*N1_ + t + 1024*i] = e[i]*inv;
}

// ---------------- y[b,i,dy,dx] = sum_p x1[b,i,p]*cf_pad[b, p-(dy-1,dx-1)] --
__global__ __launch_bounds__(256) void y_k(const float* __restrict__ x1)
{
    __shared__ float cf_s[N1_];
    __shared__ float part[8][9];
    int i = blockIdx.x, b = blockIdx.y, t = threadIdx.x;
    for (int idx = t; idx < N1_; idx += 256) cf_s[idx] = g_cf[b*N1_ + idx];
    __syncthreads();
    float a[9];
    #pragma unroll
    for (int k = 0; k < 9; k++) a[k] = 0.f;
    const float* xp = x1 + ((size_t)(b*C1_ + i))*N1_;
    for (int p = t; p < N1_; p += 256) {
        float xv = xp[p];
        int ph = p >> 6, pw = p & 63;
        #pragma unroll
        for (int dy = 0; dy < 3; dy++) {
            int qh = ph + 1 - dy;
            if ((unsigned)qh < 64u) {
                #pragma unroll
                for (int dx = 0; dx < 3; dx++) {
                    int qw = pw + 1 - dx;
                    if ((unsigned)qw < 64u)
                        a[dy*3+dx] = fmaf(xv, cf_s[(qh<<6)+qw], a[dy*3+dx]);
                }
            }
        }
    }
    #pragma unroll
    for (int k = 0; k < 9; k++) {
        float s = a[k];
        #pragma unroll
        for (int o = 16; o; o >>= 1) s += __shfl_xor_sync(~0u, s, o);
        if ((t&31) == 0) part[t>>5][k] = s;
    }
    __syncthreads();
    if (t < 9) {
        float s = 0.f;
        #pragma unroll
        for (int w = 0; w < 8; w++) s += part[w][t];
        g_y[(b*C1_+i)*9 + t] = s;
    }
}

// ---------------- pool = wch*y ; t = wt1*pool ; LN ; relu ; cw = wt2*t -----
__global__ __launch_bounds__(256) void chtail_k(
    const float* __restrict__ wch, const float* __restrict__ wt1,
    const float* __restrict__ bt1, const float* __restrict__ lng,
    const float* __restrict__ lnb, const float* __restrict__ wt2,
    const float* __restrict__ bt2)
{
    __shared__ float y_s[C1_*9];
    __shared__ float pool_s[C1_];
    __shared__ float t_s[CR_];
    int b = blockIdx.x, t = threadIdx.x;
    for (int idx = t; idx < C1_*9; idx += 256) y_s[idx] = g_y[b*C1_*9 + idx];
    __syncthreads();
    {
        float a = 0.f;
        const float* wp = wch + (size_t)t*(C1_*9);
        #pragma unroll 4
        for (int idx = 0; idx < C1_*9; idx++) a = fmaf(wp[idx], y_s[idx], a);
        pool_s[t] = a;
    }
    __syncthreads();
    if (t < CR_) {
        float tv = bt1[t];
        const float* wp = wt1 + t*C1_;
        #pragma unroll 4
        for (int c = 0; c < C1_; c++) tv = fmaf(wp[c], pool_s[c], tv);
        float s1 = tv;
        #pragma unroll
        for (int o = 16; o; o >>= 1) s1 += __shfl_xor_sync(~0u, s1, o);
        float mu = s1 * (1.f/32.f);
        float d  = tv - mu;
        float s2 = d*d;
        #pragma unroll
        for (int o = 16; o; o >>= 1) s2 += __shfl_xor_sync(~0u, s2, o);
        float var = s2 * (1.f/32.f);
        float val = d * rsqrtf(var + 1e-5f) * lng[t] + lnb[t];
        t_s[t] = fmaxf(val, 0.f);
    }
    __syncthreads();
    {
        float a = bt2[t];
        const float* wp = wt2 + t*CR_;
        #pragma unroll
        for (int j = 0; j < CR_; j++) a = fmaf(wp[j], t_s[j], a);
        g_cw[b*C1_ + t] = a;
    }
}

// ---------------------------------------------------------------------------
extern "C" void kernel_launch(void* const* d_in, const int* in_sizes, int n_in,
                              void* d_out, int out_size)
{
    (void)in_sizes; (void)n_in; (void)out_size;
    const float* x1  = (const float*)d_in[0];
    const float* x2  = (const float*)d_in[1];
    const float* wq  = (const float*)d_in[2];
    const float* wk  = (const float*)d_in[3];
    const float* wv  = (const float*)d_in[4];
    const float* wc  = (const float*)d_in[5];
    const float* wch = (const float*)d_in[6];
    const float* wt1 = (const float*)d_in[7];
    const float* bt1 = (const float*)d_in[8];
    const float* lng = (const float*)d_in[9];
    const float* lnb = (const float*)d_in[10];
    const float* wt2 = (const float*)d_in[11];
    const float* bt2 = (const float*)d_in[12];
    float* out = (float*)d_out;

    float *pq, *pk, *pkp, *pv;
    cudaGetSymbolAddress((void**)&pq,  g_q);
    cudaGetSymbolAddress((void**)&pk,  g_k);
    cudaGetSymbolAddress((void**)&pkp, g_kpart);
    cudaGetSymbolAddress((void**)&pv,  g_v);
    (void)pk;

    // convs
    conv3x3_k<<<dim3(16, 1, B_), 256>>>(x1, wq, pq, C1_, C1_, CR_, H1_, W1_, 4, 1, 0);
    conv3x3_k<<<dim3(4,  8, B_), 256>>>(x2, wk, pkp, C2_, 64, CR_, H2_, W2_, 2, 1,
                                        B_*CR_*N2_);
    reduce_k8<<<256, 256>>>();
    conv3x3_k<<<dim3(4,  8, B_), 256>>>(x2, wv, pv, C2_, C2_, C1_, H2_, W2_, 2, 8, 0);

    // channel branch
    cf_logit_k<<<dim3(N1_/256, B_), 256>>>(x1, wc);
    cf_softmax_k<<<B_, 1024>>>();
    y_k<<<dim3(C1_, B_), 256>>>(x1);
    chtail_k<<<B_, 256>>>(wch, wt1, bt1, lng, lnb, wt2, bt2);

    // attention as GEMM / softmax / GEMM
    s_gemm_k<<<dim3(N1_/128, N2_/128, B_), 256>>>();
    softmax_k<<<dim3(N1_/8, B_), 256>>>();
    o_gemm_k<<<dim3(N1_/128, C1_/128, B_), 256>>>(x1, out);
}

// round 6
// speedup vs baseline: 1.4179x; 1.2867x over previous
#include <cuda_runtime.h>

#define B_ 8
#define C1_ 256
#define C2_ 512
#define H1_ 64
#define W1_ 64
#define N1_ 4096
#define H2_ 32
#define W2_ 32
#define N2_ 1024
#define CR_ 32

typedef unsigned long long ull;

// ---------------- scratch (device globals; no allocations) ----------------
__device__ float g_q[B_*CR_*N1_];        // [b][c][m]
__device__ float g_qpart[4*B_*CR_*N1_];
__device__ float g_k[B_*CR_*N2_];        // [b][c][n]
__device__ float g_kpart[8*B_*CR_*N2_];
__device__ float g_v[B_*C1_*N2_];        // [b][c][n]
__device__ float g_vpart[4*B_*C1_*N2_];
__device__ float g_S[B_*N1_*N2_];        // scores [b][m][n]; overwritten by P
__device__ float g_logit[B_*N1_];
__device__ float g_cf[B_*N1_];
__device__ float g_y[B_*C1_*9];
__device__ float g_cw[B_*C1_];

// ---------------- f32x2 helpers -------------------------------------------
__device__ __forceinline__ ull pack2(float x, float y) {
    ull r;
    asm("mov.b64 %0, {%1, %2};" : "=l"(r) : "f"(x), "f"(y));
    return r;
}
__device__ __forceinline__ void unpack2(ull v, float& x, float& y) {
    asm("mov.b64 {%0, %1}, %2;" : "=f"(x), "=f"(y) : "l"(v));
}
__device__ __forceinline__ void ffma2(ull& d, ull a, ull b) {
    asm("fma.rn.f32x2 %0, %1, %2, %0;" : "+l"(d) : "l"(a), "l"(b));
}
__device__ __forceinline__ ull lds64(unsigned addr) {
    ull r;
    asm volatile("ld.shared.b64 %0, [%1];" : "=l"(r) : "r"(addr));
    return r;
}

// ---------------- fast exp on FMA pipe ------------------------------------
__device__ __forceinline__ float fexp(float x) {
    x = fmaxf(x, -80.f);
    float t = x * 1.4426950408889634f;
    float z = t + 12582912.f;
    int   i = __float_as_int(z) - 0x4B400000;
    float f = t - (z - 12582912.f);
    float y = f * 0.6931471805599453f;
    float p = 1.f/720.f;
    p = fmaf(p, y, 1.f/120.f);
    p = fmaf(p, y, 1.f/24.f);
    p = fmaf(p, y, 1.f/6.f);
    p = fmaf(p, y, 0.5f);
    p = fmaf(p, y, 1.f);
    p = fmaf(p, y, 1.f);
    return p * __int_as_float((i + 127) << 23);
}

// ---------------- direct conv3x3, SAME pad --------------------------------
// 16x16 spatial tile; Cout chunk = 8*COPT; thread = 8px x COPT co.
// Weights duplicated (w,w) in smem -> LDS.64 dup, zero packs for weights.
// Spatial pairs packed once per row, reused across dx and co -> FFMA2-bound.
template<int COPT, int MINB>
__global__ __launch_bounds__(256, MINB) void conv3x3_t(
    const float* __restrict__ in, const float* __restrict__ wgt,
    float* __restrict__ out, int Cin_total, int ci_count, int Cout,
    int H, int W, int tilesW, int co_groups, long slab_stride)
{
    const int CC = COPT * 8;
    __shared__ float in_s[8*324];       // [ci][18][18]
    __shared__ ull   wd[72*CC];         // [ci*9+k][co] duplicated pairs

    int t  = threadIdx.x;
    int b  = blockIdx.z;
    int co_base = (blockIdx.y % co_groups) * CC;
    int ci_g    = blockIdx.y / co_groups;
    int cib     = ci_g * ci_count;
    int tw = blockIdx.x % tilesW, th = blockIdx.x / tilesW;
    int h0 = th*16, w0 = tw*16;
    int slot = t & 31, cog = t >> 5;
    int hh = slot >> 1, ww = (slot & 1) * 8;
    int co0 = cog * COPT;
    unsigned wdb = (unsigned)__cvta_generic_to_shared(wd);

    ull acc[COPT][4];
    #pragma unroll
    for (int c = 0; c < COPT; c++)
        #pragma unroll
        for (int p = 0; p < 4; p++) acc[c][p] = 0ull;

    for (int ci0 = 0; ci0 < ci_count; ci0 += 8) {
        for (int idx = t; idx < 8*324; idx += 256) {
            int ci = idx / 324; int rem = idx - ci*324;
            int r = rem / 18;   int c = rem - r*18;
            int gh = h0 + r - 1, gw = w0 + c - 1;
            float v = 0.f;
            if (gh >= 0 && gh < H && gw >= 0 && gw < W)
                v = in[((size_t)(b*Cin_total + cib+ci0+ci)*H + gh)*W + gw];
            in_s[idx] = v;
        }
        for (int idx = t; idx < 72*CC; idx += 256) {
            int co = idx / 72; int r = idx - co*72;     // r = ci*9+k
            float w = wgt[(size_t)(co_base+co)*Cin_total*9
                          + (size_t)(cib+ci0)*9 + r];
            wd[r*CC + co] = pack2(w, w);
        }
        __syncthreads();
        #pragma unroll
        for (int ci = 0; ci < 8; ci++) {
            #pragma unroll
            for (int r = 0; r < 3; r++) {
                float xrow[10];
                #pragma unroll
                for (int c = 0; c < 10; c++)
                    xrow[c] = in_s[ci*324 + (hh+r)*18 + ww + c];
                ull pr[9];
                #pragma unroll
                for (int j = 0; j < 9; j++) pr[j] = pack2(xrow[j], xrow[j+1]);
                #pragma unroll
                for (int dx = 0; dx < 3; dx++) {
                    int k = r*3 + dx;
                    #pragma unroll
                    for (int c = 0; c < COPT; c++) {
                        ull w2 = lds64(wdb +
                            (unsigned)(((ci*9+k)*CC + co0 + c) << 3));
                        #pragma unroll
                        for (int p = 0; p < 4; p++)
                            ffma2(acc[c][p], w2, pr[dx + 2*p]);
                    }
                }
            }
        }
        __syncthreads();
    }
    float* op = out + (size_t)ci_g * slab_stride;
    #pragma unroll
    for (int c = 0; c < COPT; c++) {
        int co = co_base + co0 + c;
        float* row = op + ((size_t)(b*Cout + co)*H + h0+hh)*W + w0 + ww;
        #pragma unroll
        for (int p = 0; p < 4; p++) {
            float x, y; unpack2(acc[c][p], x, y);
            *(float2*)(row + 2*p) = make_float2(x, y);
        }
    }
}

// ---------------- generic slab reduce -------------------------------------
__global__ __launch_bounds__(256) void reduce_slabs(const float4* __restrict__ part,
                                                    float4* __restrict__ out,
                                                    int nslab, int n4)
{
    int i = blockIdx.x*256 + threadIdx.x;
    if (i >= n4) return;
    float4 s = part[i];
    for (int g = 1; g < nslab; g++) {
        float4 a = part[(size_t)g*n4 + i];
        s.x += a.x; s.y += a.y; s.z += a.z; s.w += a.w;
    }
    out[i] = s;
}

// ---------------- S[m][n] = sum_c q[c][m] k[c][n]  (128x128 tiles) --------
__global__ __launch_bounds__(256, 2) void s_gemm_k()
{
    __shared__ float q_s[32*128];
    __shared__ float k_s[32*128];
    int t = threadIdx.x, b = blockIdx.z;
    int m0 = blockIdx.x*128, n0 = blockIdx.y*128;
    for (int i = t; i < 1024; i += 256) {
        int c = i >> 5, j = i & 31;
        ((float4*)q_s)[i] = *(const float4*)(g_q + ((size_t)(b*CR_ + c))*N1_ + m0 + 4*j);
        ((float4*)k_s)[i] = *(const float4*)(g_k + ((size_t)(b*CR_ + c))*N2_ + n0 + 4*j);
    }
    __syncthreads();
    int tn = t & 15, tm = t >> 4;
    unsigned kb = (unsigned)__cvta_generic_to_shared(k_s);
    ull acc2[8][4];
    #pragma unroll
    for (int im = 0; im < 8; im++)
        #pragma unroll
        for (int jn = 0; jn < 4; jn++) acc2[im][jn] = 0ull;
    #pragma unroll 4
    for (int c = 0; c < 32; c++) {
        ull ad[8], bd[4];
        #pragma unroll
        for (int im = 0; im < 8; im++) {
            float qv = q_s[c*128 + tm*8 + im];
            ad[im] = pack2(qv, qv);
        }
        #pragma unroll
        for (int jn = 0; jn < 4; jn++)
            bd[jn] = lds64(kb + (unsigned)((c*128 + tn*2 + 32*jn) << 2));
        #pragma unroll
        for (int im = 0; im < 8; im++)
            #pragma unroll
            for (int jn = 0; jn < 4; jn++)
                ffma2(acc2[im][jn], ad[im], bd[jn]);
    }
    #pragma unroll
    for (int im = 0; im < 8; im++) {
        float* row = g_S + ((size_t)(b*N1_) + m0 + tm*8 + im)*N2_ + n0;
        #pragma unroll
        for (int jn = 0; jn < 4; jn++) {
            float x, y; unpack2(acc2[im][jn], x, y);
            *(float2*)(row + tn*2 + 32*jn) = make_float2(x, y);
        }
    }
}

// ---------------- row softmax over n; normalize in place ------------------
__global__ __launch_bounds__(256) void softmax_k()
{
    int b = blockIdx.y;
    int m = blockIdx.x*8 + (threadIdx.x >> 5);
    int lane = threadIdx.x & 31;
    float4* row = (float4*)(g_S + ((size_t)(b*N1_) + m)*N2_);
    float4 v[8];
    #pragma unroll
    for (int j = 0; j < 8; j++) v[j] = row[lane + 32*j];
    float mx = -3e38f;
    #pragma unroll
    for (int j = 0; j < 8; j++)
        mx = fmaxf(mx, fmaxf(fmaxf(v[j].x, v[j].y), fmaxf(v[j].z, v[j].w)));
    #pragma unroll
    for (int o = 16; o; o >>= 1) mx = fmaxf(mx, __shfl_xor_sync(~0u, mx, o));
    float s = 0.f;
    #pragma unroll
    for (int j = 0; j < 8; j++) {
        v[j].x = fexp(v[j].x - mx); v[j].y = fexp(v[j].y - mx);
        v[j].z = fexp(v[j].z - mx); v[j].w = fexp(v[j].w - mx);
        s += v[j].x + v[j].y + v[j].z + v[j].w;
    }
    #pragma unroll
    for (int o = 16; o; o >>= 1) s += __shfl_xor_sync(~0u, s, o);
    float inv = 1.f / s;
    #pragma unroll
    for (int j = 0; j < 8; j++) {
        v[j].x *= inv; v[j].y *= inv; v[j].z *= inv; v[j].w *= inv;
        row[lane + 32*j] = v[j];
    }
}

// ---------------- O[c][m] = sum_n V[c][n] P[m][n]; fused epilogue ---------
#define OP_  134     // b_s pitch (floats, even for lds64)
#define OPA_ 130     // a2_s pitch (ull)
__global__ __launch_bounds__(256, 2) void o_gemm_k(const float* __restrict__ x1,
                                                   float* __restrict__ out)
{
    __shared__ ull   a2_s[16*OPA_];  // [n][c] duplicated V
    __shared__ float b_s[16*OP_];    // [n][m] P
    int t = threadIdx.x, b = blockIdx.z;
    int m0 = blockIdx.x*128, c0 = blockIdx.y*128;
    int tmq = t & 15, tcq = t >> 4;
    int rr = t >> 1, nh = (t & 1)*8;
    const float* vsrc = g_v + ((size_t)(b*C1_ + c0 + rr))*N2_ + nh;
    const float* psrc = g_S + ((size_t)(b*N1_ + m0 + rr))*N2_ + nh;
    unsigned bb = (unsigned)__cvta_generic_to_shared(b_s);
    ull acc2[8][4];
    #pragma unroll
    for (int i = 0; i < 8; i++)
        #pragma unroll
        for (int j = 0; j < 4; j++) acc2[i][j] = 0ull;

    for (int nb = 0; nb < N2_; nb += 16) {
        float4 a0 = *(const float4*)(vsrc + nb);
        float4 a1 = *(const float4*)(vsrc + nb + 4);
        float4 p0 = *(const float4*)(psrc + nb);
        float4 p1 = *(const float4*)(psrc + nb + 4);
        __syncthreads();
        a2_s[(nh+0)*OPA_ + rr] = pack2(a0.x, a0.x);
        a2_s[(nh+1)*OPA_ + rr] = pack2(a0.y, a0.y);
        a2_s[(nh+2)*OPA_ + rr] = pack2(a0.z, a0.z);
        a2_s[(nh+3)*OPA_ + rr] = pack2(a0.w, a0.w);
        a2_s[(nh+4)*OPA_ + rr] = pack2(a1.x, a1.x);
        a2_s[(nh+5)*OPA_ + rr] = pack2(a1.y, a1.y);
        a2_s[(nh+6)*OPA_ + rr] = pack2(a1.z, a1.z);
        a2_s[(nh+7)*OPA_ + rr] = pack2(a1.w, a1.w);
        b_s[(nh+0)*OP_ + rr] = p0.x; b_s[(nh+1)*OP_ + rr] = p0.y;
        b_s[(nh+2)*OP_ + rr] = p0.z; b_s[(nh+3)*OP_ + rr] = p0.w;
        b_s[(nh+4)*OP_ + rr] = p1.x; b_s[(nh+5)*OP_ + rr] = p1.y;
        b_s[(nh+6)*OP_ + rr] = p1.z; b_s[(nh+7)*OP_ + rr] = p1.w;
        __syncthreads();
        #pragma unroll 4
        for (int n = 0; n < 16; n++) {
            ull bd[4];
            #pragma unroll
            for (int j = 0; j < 4; j++)
                bd[j] = lds64(bb + (unsigned)((n*OP_ + tmq*2 + 32*j) << 2));
            #pragma unroll
            for (int i = 0; i < 8; i++) {
                ull ad = a2_s[n*OPA_ + tcq*8 + i];
                #pragma unroll
                for (int j = 0; j < 4; j++)
                    ffma2(acc2[i][j], ad, bd[j]);
            }
        }
    }
    float wm[8];
    #pragma unroll
    for (int i = 0; i < 8; i++) wm[i] = 1.f + g_cw[b*C1_ + c0 + tcq*8 + i];
    #pragma unroll
    for (int i = 0; i < 8; i++)
        #pragma unroll
        for (int j = 0; j < 4; j++) {
            float x, y; unpack2(acc2[i][j], x, y);
            size_t off = ((size_t)(b*C1_ + c0 + tcq*8 + i))*N1_ + m0 + tmq*2 + 32*j;
            float2 xv = *(const float2*)(x1 + off);
            *(float2*)(out + off) = make_float2(fmaf(xv.x, wm[i], x),
                                                fmaf(xv.y, wm[i], y));
        }
}

// ---------------- channel branch: cf logits (1x1 conv) --------------------
__global__ __launch_bounds__(256) void cf_logit_k(const float* __restrict__ x1,
                                                  const float* __restrict__ wc)
{
    __shared__ float wc_s[C1_];
    int t = threadIdx.x, b = blockIdx.y;
    wc_s[t] = wc[t];
    __syncthreads();
    int n = blockIdx.x*256 + t;
    const float* xp = x1 + (size_t)b*C1_*N1_ + n;
    float s0 = 0.f, s1 = 0.f, s2 = 0.f, s3 = 0.f;
    #pragma unroll 4
    for (int c = 0; c < C1_; c += 4) {
        s0 = fmaf(wc_s[c+0], __ldg(xp + (size_t)(c+0)*N1_), s0);
        s1 = fmaf(wc_s[c+1], __ldg(xp + (size_t)(c+1)*N1_), s1);
        s2 = fmaf(wc_s[c+2], __ldg(xp + (size_t)(c+2)*N1_), s2);
        s3 = fmaf(wc_s[c+3], __ldg(xp + (size_t)(c+3)*N1_), s3);
    }
    g_logit[b*N1_ + n] = (s0 + s1) + (s2 + s3);
}

// ---------------- cf softmax over N1 (per b) -------------------------------
__global__ __launch_bounds__(1024) void cf_softmax_k()
{
    int b = blockIdx.x, t = threadIdx.x;
    __shared__ float red[32];
    float v[4];
    #pragma unroll
    for (int i = 0; i < 4; i++) v[i] = g_logit[b*N1_ + t + 1024*i];
    float mx = fmaxf(fmaxf(v[0],v[1]), fmaxf(v[2],v[3]));
    #pragma unroll
    for (int o = 16; o; o >>= 1) mx = fmaxf(mx, __shfl_xor_sync(~0u, mx, o));
    if ((t&31) == 0) red[t>>5] = mx;
    __syncthreads();
    if (t < 32) {
        float m2 = red[t];
        #pragma unroll
        for (int o = 16; o; o >>= 1) m2 = fmaxf(m2, __shfl_xor_sync(~0u, m2, o));
        red[t] = m2;
    }
    __syncthreads();
    mx = red[0];
    __syncthreads();
    float e[4]; float s = 0.f;
    #pragma unroll
    for (int i = 0; i < 4; i++) { e[i] = fexp(v[i]-mx); s += e[i]; }
    #pragma unroll
    for (int o = 16; o; o >>= 1) s += __shfl_xor_sync(~0u, s, o);
    if ((t&31) == 0) red[t>>5] = s;
    __syncthreads();
    if (t < 32) {
        float s2 = red[t];
        #pragma unroll
        for (int o = 16; o; o >>= 1) s2 += __shfl_xor_sync(~0u, s2, o);
        red[t] = s2;
    }
    __syncthreads();
    float inv = 1.f / red[0];
    #pragma unroll
    for (int i = 0; i < 4; i++) g_cf[b*N1_ + t + 1024*i] = e[i]*inv;
}

// ---------------- y[b,i,dy,dx] = sum_p x1[b,i,p]*cf_pad[b, p-(dy-1,dx-1)] --
__global__ __launch_bounds__(256) void y_k(const float* __restrict__ x1)
{
    __shared__ float cf_s[N1_];
    __shared__ float part[8][9];
    int i = blockIdx.x, b = blockIdx.y, t = threadIdx.x;
    for (int idx = t; idx < N1_; idx += 256) cf_s[idx] = g_cf[b*N1_ + idx];
    __syncthreads();
    float a[9];
    #pragma unroll
    for (int k = 0; k < 9; k++) a[k] = 0.f;
    const float* xp = x1 + ((size_t)(b*C1_ + i))*N1_;
    for (int p = t; p < N1_; p += 256) {
        float xv = xp[p];
        int ph = p >> 6, pw = p & 63;
        #pragma unroll
        for (int dy = 0; dy < 3; dy++) {
            int qh = ph + 1 - dy;
            if ((unsigned)qh < 64u) {
                #pragma unroll
                for (int dx = 0; dx < 3; dx++) {
                    int qw = pw + 1 - dx;
                    if ((unsigned)qw < 64u)
                        a[dy*3+dx] = fmaf(xv, cf_s[(qh<<6)+qw], a[dy*3+dx]);
                }
            }
        }
    }
    #pragma unroll
    for (int k = 0; k < 9; k++) {
        float s = a[k];
        #pragma unroll
        for (int o = 16; o; o >>= 1) s += __shfl_xor_sync(~0u, s, o);
        if ((t&31) == 0) part[t>>5][k] = s;
    }
    __syncthreads();
    if (t < 9) {
        float s = 0.f;
        #pragma unroll
        for (int w = 0; w < 8; w++) s += part[w][t];
        g_y[(b*C1_+i)*9 + t] = s;
    }
}

// ---------------- pool = wch*y ; t = wt1*pool ; LN ; relu ; cw = wt2*t -----
__global__ __launch_bounds__(256) void chtail_k(
    const float* __restrict__ wch, const float* __restrict__ wt1,
    const float* __restrict__ bt1, const float* __restrict__ lng,
    const float* __restrict__ lnb, const float* __restrict__ wt2,
    const float* __restrict__ bt2)
{
    __shared__ float y_s[C1_*9];
    __shared__ float pool_s[C1_];
    __shared__ float t_s[CR_];
    int b = blockIdx.x, t = threadIdx.x;
    for (int idx = t; idx < C1_*9; idx += 256) y_s[idx] = g_y[b*C1_*9 + idx];
    __syncthreads();
    {
        float a = 0.f;
        const float* wp = wch + (size_t)t*(C1_*9);
        #pragma unroll 4
        for (int idx = 0; idx < C1_*9; idx++) a = fmaf(wp[idx], y_s[idx], a);
        pool_s[t] = a;
    }
    __syncthreads();
    if (t < CR_) {
        float tv = bt1[t];
        const float* wp = wt1 + t*C1_;
        #pragma unroll 4
        for (int c = 0; c < C1_; c++) tv = fmaf(wp[c], pool_s[c], tv);
        float s1 = tv;
        #pragma unroll
        for (int o = 16; o; o >>= 1) s1 += __shfl_xor_sync(~0u, s1, o);
        float mu = s1 * (1.f/32.f);
        float d  = tv - mu;
        float s2 = d*d;
        #pragma unroll
        for (int o = 16; o; o >>= 1) s2 += __shfl_xor_sync(~0u, s2, o);
        float var = s2 * (1.f/32.f);
        float val = d * rsqrtf(var + 1e-5f) * lng[t] + lnb[t];
        t_s[t] = fmaxf(val, 0.f);
    }
    __syncthreads();
    {
        float a = bt2[t];
        const float* wp = wt2 + t*CR_;
        #pragma unroll
        for (int j = 0; j < CR_; j++) a = fmaf(wp[j], t_s[j], a);
        g_cw[b*C1_ + t] = a;
    }
}

// ---------------------------------------------------------------------------
extern "C" void kernel_launch(void* const* d_in, const int* in_sizes, int n_in,
                              void* d_out, int out_size)
{
    (void)in_sizes; (void)n_in; (void)out_size;
    const float* x1  = (const float*)d_in[0];
    const float* x2  = (const float*)d_in[1];
    const float* wq  = (const float*)d_in[2];
    const float* wk  = (const float*)d_in[3];
    const float* wv  = (const float*)d_in[4];
    const float* wc  = (const float*)d_in[5];
    const float* wch = (const float*)d_in[6];
    const float* wt1 = (const float*)d_in[7];
    const float* bt1 = (const float*)d_in[8];
    const float* lng = (const float*)d_in[9];
    const float* lnb = (const float*)d_in[10];
    const float* wt2 = (const float*)d_in[11];
    const float* bt2 = (const float*)d_in[12];
    float* out = (float*)d_out;

    float *pq, *pqp, *pk, *pkp, *pv, *pvp;
    cudaGetSymbolAddress((void**)&pq,  g_q);
    cudaGetSymbolAddress((void**)&pqp, g_qpart);
    cudaGetSymbolAddress((void**)&pk,  g_k);
    cudaGetSymbolAddress((void**)&pkp, g_kpart);
    cudaGetSymbolAddress((void**)&pv,  g_v);
    cudaGetSymbolAddress((void**)&pvp, g_vpart);

    // conv_v: Cin 512 split 4x128, Cout 256 in 4 blocks of 64 (COPT=8)
    conv3x3_t<8,2><<<dim3(4, 16, B_), 256>>>(x2, wv, pvp, C2_, 128, C1_,
                                             H2_, W2_, 2, 4, (long)B_*C1_*N2_);
    reduce_slabs<<<2048, 256>>>((const float4*)pvp, (float4*)pv, 4, B_*C1_*N2_/4);

    // conv_q: Cin 256 split 4x64, Cout 32 (COPT=4)
    conv3x3_t<4,3><<<dim3(16, 4, B_), 256>>>(x1, wq, pqp, C1_, 64, CR_,
                                             H1_, W1_, 4, 1, (long)B_*CR_*N1_);
    reduce_slabs<<<1024, 256>>>((const float4*)pqp, (float4*)pq, 4, B_*CR_*N1_/4);

    // conv_k: Cin 512 split 8x64, Cout 32 (COPT=4)
    conv3x3_t<4,3><<<dim3(4, 8, B_), 256>>>(x2, wk, pkp, C2_, 64, CR_,
                                            H2_, W2_, 2, 1, (long)B_*CR_*N2_);
    reduce_slabs<<<256, 256>>>((const float4*)pkp, (float4*)pk, 8, B_*CR_*N2_/4);

    // channel branch
    cf_logit_k<<<dim3(N1_/256, B_), 256>>>(x1, wc);
    cf_softmax_k<<<B_, 1024>>>();
    y_k<<<dim3(C1_, B_), 256>>>(x1);
    chtail_k<<<B_, 256>>>(wch, wt1, bt1, lng, lnb, wt2, bt2);

    // attention as GEMM / softmax / GEMM
    s_gemm_k<<<dim3(N1_/128, N2_/128, B_), 256>>>();
    softmax_k<<<dim3(N1_/8, B_), 256>>>();
    o_gemm_k<<<dim3(N1_/128, C1_/128, B_), 256>>>(x1, out);
}

// round 9
// speedup vs baseline: 1.7360x; 1.2244x over previous
#include <cuda_runtime.h>
#include <cuda_bf16.h>
#include <cstdint>

#define B_ 8
#define C1_ 256
#define C2_ 512
#define H1_ 64
#define W1_ 64
#define N1_ 4096
#define H2_ 32
#define W2_ 32
#define N2_ 1024
#define CR_ 32

typedef unsigned long long ull;

// ---------------- scratch (device globals; no allocations) ----------------
__device__ float g_q[B_*CR_*N1_];        // [b][c][m]
__device__ float g_qpart[4*B_*CR_*N1_];
__device__ float g_k[B_*CR_*N2_];        // [b][c][n]
__device__ float g_kpart[8*B_*CR_*N2_];
__device__ float g_v[B_*C1_*N2_];        // [b][c][n]
__device__ float g_vpart[4*B_*C1_*N2_];
__device__ float g_S[B_*N1_*N2_];        // scores [b][m][n]
__device__ __nv_bfloat16 g_Ph[B_*N1_*N2_];  // P hi/lo split
__device__ __nv_bfloat16 g_Pl[B_*N1_*N2_];
__device__ __nv_bfloat16 g_vh[B_*C1_*N2_];  // V hi/lo split
__device__ __nv_bfloat16 g_vl[B_*C1_*N2_];
__device__ float g_logit[B_*N1_];
__device__ float g_cf[B_*N1_];
__device__ float g_y[B_*C1_*9];
__device__ float g_cw[B_*C1_];

// ---------------- f32x2 helpers -------------------------------------------
__device__ __forceinline__ ull pack2(float x, float y) {
    ull r;
    asm("mov.b64 %0, {%1, %2};" : "=l"(r) : "f"(x), "f"(y));
    return r;
}
__device__ __forceinline__ void unpack2(ull v, float& x, float& y) {
    asm("mov.b64 {%0, %1}, %2;" : "=f"(x), "=f"(y) : "l"(v));
}
__device__ __forceinline__ void ffma2(ull& d, ull a, ull b) {
    asm("fma.rn.f32x2 %0, %1, %2, %0;" : "+l"(d) : "l"(a), "l"(b));
}
__device__ __forceinline__ ull lds64(unsigned addr) {
    ull r;
    asm volatile("ld.shared.b64 %0, [%1];" : "=l"(r) : "r"(addr));
    return r;
}
__device__ __forceinline__ uint32_t smem_u32(const void* p) {
    uint32_t a;
    asm("{ .reg .u64 t; cvta.to.shared.u64 t, %1; cvt.u32.u64 %0, t; }"
        : "=r"(a) : "l"(p));
    return a;
}

// ---------------- mma.sync helpers (plain-PTX tensor path) ----------------
__device__ __forceinline__ void ldmx4(uint32_t* r, unsigned a) {
    asm volatile("ldmatrix.sync.aligned.m8n8.x4.shared.b16 {%0,%1,%2,%3}, [%4];"
        : "=r"(r[0]), "=r"(r[1]), "=r"(r[2]), "=r"(r[3]) : "r"(a));
}
__device__ __forceinline__ void mma16816(float* d, const uint32_t* a,
                                         const uint32_t* b) {
    asm volatile(
        "mma.sync.aligned.m16n8k16.row.col.f32.bf16.bf16.f32 "
        "{%0,%1,%2,%3}, {%4,%5,%6,%7}, {%8,%9}, {%0,%1,%2,%3};"
        : "+f"(d[0]), "+f"(d[1]), "+f"(d[2]), "+f"(d[3])
        : "r"(a[0]), "r"(a[1]), "r"(a[2]), "r"(a[3]), "r"(b[0]), "r"(b[1]));
}

// ---------------- fast exp on FMA pipe ------------------------------------
__device__ __forceinline__ float fexp(float x) {
    x = fmaxf(x, -80.f);
    float t = x * 1.4426950408889634f;
    float z = t + 12582912.f;
    int   i = __float_as_int(z) - 0x4B400000;
    float f = t - (z - 12582912.f);
    float y = f * 0.6931471805599453f;
    float p = 1.f/720.f;
    p = fmaf(p, y, 1.f/120.f);
    p = fmaf(p, y, 1.f/24.f);
    p = fmaf(p, y, 1.f/6.f);
    p = fmaf(p, y, 0.5f);
    p = fmaf(p, y, 1.f);
    p = fmaf(p, y, 1.f);
    return p * __int_as_float((i + 127) << 23);
}

// ---------------- direct conv3x3, SAME pad (f32x2, weights duplicated) ----
template<int COPT, int MINB>
__global__ __launch_bounds__(256, MINB) void conv3x3_t(
    const float* __restrict__ in, const float* __restrict__ wgt,
    float* __restrict__ out, int Cin_total, int ci_count, int Cout,
    int H, int W, int tilesW, int co_groups, long slab_stride)
{
    const int CC = COPT * 8;
    __shared__ float in_s[8*324];       // [ci][18][18]
    __shared__ ull   wd[72*CC];         // [ci*9+k][co] duplicated pairs

    int t  = threadIdx.x;
    int b  = blockIdx.z;
    int co_base = (blockIdx.y % co_groups) * CC;
    int ci_g    = blockIdx.y / co_groups;
    int cib     = ci_g * ci_count;
    int tw = blockIdx.x % tilesW, th = blockIdx.x / tilesW;
    int h0 = th*16, w0 = tw*16;
    int slot = t & 31, cog = t >> 5;
    int hh = slot >> 1, ww = (slot & 1) * 8;
    int co0 = cog * COPT;
    unsigned wdb = (unsigned)__cvta_generic_to_shared(wd);

    ull acc[COPT][4];
    #pragma unroll
    for (int c = 0; c < COPT; c++)
        #pragma unroll
        for (int p = 0; p < 4; p++) acc[c][p] = 0ull;

    for (int ci0 = 0; ci0 < ci_count; ci0 += 8) {
        for (int idx = t; idx < 8*324; idx += 256) {
            int ci = idx / 324; int rem = idx - ci*324;
            int r = rem / 18;   int c = rem - r*18;
            int gh = h0 + r - 1, gw = w0 + c - 1;
            float v = 0.f;
            if (gh >= 0 && gh < H && gw >= 0 && gw < W)
                v = in[((size_t)(b*Cin_total + cib+ci0+ci)*H + gh)*W + gw];
            in_s[idx] = v;
        }
        for (int idx = t; idx < 72*CC; idx += 256) {
            int co = idx / 72; int r = idx - co*72;
            float w = wgt[(size_t)(co_base+co)*Cin_total*9
                          + (size_t)(cib+ci0)*9 + r];
            wd[r*CC + co] = pack2(w, w);
        }
        __syncthreads();
        #pragma unroll
        for (int ci = 0; ci < 8; ci++) {
            #pragma unroll
            for (int r = 0; r < 3; r++) {
                float xrow[10];
                #pragma unroll
                for (int c = 0; c < 10; c++)
                    xrow[c] = in_s[ci*324 + (hh+r)*18 + ww + c];
                ull pr[9];
                #pragma unroll
                for (int j = 0; j < 9; j++) pr[j] = pack2(xrow[j], xrow[j+1]);
                #pragma unroll
                for (int dx = 0; dx < 3; dx++) {
                    int k = r*3 + dx;
                    #pragma unroll
                    for (int c = 0; c < COPT; c++) {
                        ull w2 = lds64(wdb +
                            (unsigned)(((ci*9+k)*CC + co0 + c) << 3));
                        #pragma unroll
                        for (int p = 0; p < 4; p++)
                            ffma2(acc[c][p], w2, pr[dx + 2*p]);
                    }
                }
            }
        }
        __syncthreads();
    }
    float* op = out + (size_t)ci_g * slab_stride;
    #pragma unroll
    for (int c = 0; c < COPT; c++) {
        int co = co_base + co0 + c;
        float* row = op + ((size_t)(b*Cout + co)*H + h0+hh)*W + w0 + ww;
        #pragma unroll
        for (int p = 0; p < 4; p++) {
            float x, y; unpack2(acc[c][p], x, y);
            *(float2*)(row + 2*p) = make_float2(x, y);
        }
    }
}

// ---------------- generic slab reduce -------------------------------------
__global__ __launch_bounds__(256) void reduce_slabs(const float4* __restrict__ part,
                                                    float4* __restrict__ out,
                                                    int nslab, int n4)
{
    int i = blockIdx.x*256 + threadIdx.x;
    if (i >= n4) return;
    float4 s = part[i];
    for (int g = 1; g < nslab; g++) {
        float4 a = part[(size_t)g*n4 + i];
        s.x += a.x; s.y += a.y; s.z += a.z; s.w += a.w;
    }
    out[i] = s;
}

// ---------------- V fp32 -> bf16 hi/lo ------------------------------------
__global__ __launch_bounds__(256) void vconv_k()
{
    int i = blockIdx.x*256 + threadIdx.x;       // float4 index
    float4 v = ((const float4*)g_v)[i];
    __nv_bfloat162 h0, h1, l0, l1;
    h0.x = __float2bfloat16_rn(v.x); h0.y = __float2bfloat16_rn(v.y);
    h1.x = __float2bfloat16_rn(v.z); h1.y = __float2bfloat16_rn(v.w);
    l0.x = __float2bfloat16_rn(v.x - __bfloat162float(h0.x));
    l0.y = __float2bfloat16_rn(v.y - __bfloat162float(h0.y));
    l1.x = __float2bfloat16_rn(v.z - __bfloat162float(h1.x));
    l1.y = __float2bfloat16_rn(v.w - __bfloat162float(h1.y));
    ((__nv_bfloat162*)g_vh)[2*i]   = h0;
    ((__nv_bfloat162*)g_vh)[2*i+1] = h1;
    ((__nv_bfloat162*)g_vl)[2*i]   = l0;
    ((__nv_bfloat162*)g_vl)[2*i+1] = l1;
}

// ---------------- S[m][n] = sum_c q[c][m] k[c][n]  (128x128 tiles) --------
__global__ __launch_bounds__(256, 2) void s_gemm_k()
{
    __shared__ float q_s[32*128];
    __shared__ float k_s[32*128];
    int t = threadIdx.x, b = blockIdx.z;
    int m0 = blockIdx.x*128, n0 = blockIdx.y*128;
    for (int i = t; i < 1024; i += 256) {
        int c = i >> 5, j = i & 31;
        ((float4*)q_s)[i] = *(const float4*)(g_q + ((size_t)(b*CR_ + c))*N1_ + m0 + 4*j);
        ((float4*)k_s)[i] = *(const float4*)(g_k + ((size_t)(b*CR_ + c))*N2_ + n0 + 4*j);
    }
    __syncthreads();
    int tn = t & 15, tm = t >> 4;
    unsigned kb = (unsigned)__cvta_generic_to_shared(k_s);
    ull acc2[8][4];
    #pragma unroll
    for (int im = 0; im < 8; im++)
        #pragma unroll
        for (int jn = 0; jn < 4; jn++) acc2[im][jn] = 0ull;
    #pragma unroll 4
    for (int c = 0; c < 32; c++) {
        ull ad[8], bd[4];
        #pragma unroll
        for (int im = 0; im < 8; im++) {
            float qv = q_s[c*128 + tm*8 + im];
            ad[im] = pack2(qv, qv);
        }
        #pragma unroll
        for (int jn = 0; jn < 4; jn++)
            bd[jn] = lds64(kb + (unsigned)((c*128 + tn*2 + 32*jn) << 2));
        #pragma unroll
        for (int im = 0; im < 8; im++)
            #pragma unroll
            for (int jn = 0; jn < 4; jn++)
                ffma2(acc2[im][jn], ad[im], bd[jn]);
    }
    #pragma unroll
    for (int im = 0; im < 8; im++) {
        float* row = g_S + ((size_t)(b*N1_) + m0 + tm*8 + im)*N2_ + n0;
        #pragma unroll
        for (int jn = 0; jn < 4; jn++) {
            float x, y; unpack2(acc2[im][jn], x, y);
            *(float2*)(row + tn*2 + 32*jn) = make_float2(x, y);
        }
    }
}

// ---------------- row softmax over n; emit P as bf16 hi/lo ----------------
__global__ __launch_bounds__(256) void softmax_k()
{
    int b = blockIdx.y;
    int m = blockIdx.x*8 + (threadIdx.x >> 5);
    int lane = threadIdx.x & 31;
    size_t base = ((size_t)(b*N1_) + m)*N2_;
    const float4* row = (const float4*)(g_S + base);
    float4 v[8];
    #pragma unroll
    for (int j = 0; j < 8; j++) v[j] = row[lane + 32*j];
    float mx = -3e38f;
    #pragma unroll
    for (int j = 0; j < 8; j++)
        mx = fmaxf(mx, fmaxf(fmaxf(v[j].x, v[j].y), fmaxf(v[j].z, v[j].w)));
    #pragma unroll
    for (int o = 16; o; o >>= 1) mx = fmaxf(mx, __shfl_xor_sync(~0u, mx, o));
    float s = 0.f;
    #pragma unroll
    for (int j = 0; j < 8; j++) {
        v[j].x = fexp(v[j].x - mx); v[j].y = fexp(v[j].y - mx);
        v[j].z = fexp(v[j].z - mx); v[j].w = fexp(v[j].w - mx);
        s += v[j].x + v[j].y + v[j].z + v[j].w;
    }
    #pragma unroll
    for (int o = 16; o; o >>= 1) s += __shfl_xor_sync(~0u, s, o);
    float inv = 1.f / s;
    __nv_bfloat162* ph = (__nv_bfloat162*)(g_Ph + base);
    __nv_bfloat162* pl = (__nv_bfloat162*)(g_Pl + base);
    #pragma unroll
    for (int j = 0; j < 8; j++) {
        float a = v[j].x*inv, c = v[j].y*inv, d = v[j].z*inv, e = v[j].w*inv;
        __nv_bfloat162 h0, h1, l0, l1;
        h0.x = __float2bfloat16_rn(a); h0.y = __float2bfloat16_rn(c);
        h1.x = __float2bfloat16_rn(d); h1.y = __float2bfloat16_rn(e);
        l0.x = __float2bfloat16_rn(a - __bfloat162float(h0.x));
        l0.y = __float2bfloat16_rn(c - __bfloat162float(h0.y));
        l1.x = __float2bfloat16_rn(d - __bfloat162float(h1.x));
        l1.y = __float2bfloat16_rn(e - __bfloat162float(h1.y));
        int q = lane + 32*j;
        ph[2*q] = h0; ph[2*q+1] = h1;
        pl[2*q] = l0; pl[2*q+1] = l1;
    }
}

// ---------------- mma.sync O-GEMM: O[c][m] = sum_n V[c][n] P[m][n] --------
// CTA tile 128c x 128m, K=1024 in chunks of 32. hi/lo bf16 split, 3 products.
// smem bf16 tiles [128][40] (stride 20 words -> conflict-free ldmatrix).
#define OSTR 40
__global__ __launch_bounds__(256) void o_mma_k(const float* __restrict__ x1,
                                               float* __restrict__ out)
{
    __shared__ __nv_bfloat16 Ah_s[128*OSTR], Al_s[128*OSTR];
    __shared__ __nv_bfloat16 Bh_s[128*OSTR], Bl_s[128*OSTR];
    int t = threadIdx.x, b = blockIdx.z;
    int m0 = blockIdx.x*128, c0 = blockIdx.y*128;
    int lane = t & 31, wid = t >> 5;
    int wc = wid >> 2, wm = wid & 3;          // 2 x 4 warp grid (c x m)
    int r = t >> 1, half = t & 1;             // 128 rows x 2 halves of 16 elts

    const __nv_bfloat16* srcAh = g_vh + ((size_t)(b*C1_ + c0 + r))*N2_ + half*16;
    const __nv_bfloat16* srcAl = g_vl + ((size_t)(b*C1_ + c0 + r))*N2_ + half*16;
    const __nv_bfloat16* srcBh = g_Ph + ((size_t)(b*N1_ + m0 + r))*N2_ + half*16;
    const __nv_bfloat16* srcBl = g_Pl + ((size_t)(b*N1_ + m0 + r))*N2_ + half*16;
    unsigned dA_h = smem_u32(Ah_s) + (unsigned)((r*OSTR + half*16) * 2);
    unsigned dA_l = smem_u32(Al_s) + (unsigned)((r*OSTR + half*16) * 2);
    unsigned dB_h = smem_u32(Bh_s) + (unsigned)((r*OSTR + half*16) * 2);
    unsigned dB_l = smem_u32(Bl_s) + (unsigned)((r*OSTR + half*16) * 2);

    // ldmatrix base addresses
    unsigned aAh = smem_u32(Ah_s), aAl = smem_u32(Al_s);
    unsigned aBh = smem_u32(Bh_s), aBl = smem_u32(Bl_s);
    int arow = wc*64 + (lane & 15);               // + ct*16
    int acol = (lane >> 4) * 8;                   // + kk*16
    int brow = wm*32 + (lane & 7) + ((lane >> 4) << 3);   // + pair*16
    int bcol = ((lane >> 3) & 1) * 8;                     // + kk*16

    float acc[4][4][4];
    #pragma unroll
    for (int i = 0; i < 4; i++)
        #pragma unroll
        for (int j = 0; j < 4; j++)
            #pragma unroll
            for (int k = 0; k < 4; k++) acc[i][j][k] = 0.f;

    for (int nb = 0; nb < N2_; nb += 32) {
        uint4 vah0 = *(const uint4*)(srcAh + nb);
        uint4 vah1 = *(const uint4*)(srcAh + nb + 8);
        uint4 val0 = *(const uint4*)(srcAl + nb);
        uint4 val1 = *(const uint4*)(srcAl + nb + 8);
        uint4 vbh0 = *(const uint4*)(srcBh + nb);
        uint4 vbh1 = *(const uint4*)(srcBh + nb + 8);
        uint4 vbl0 = *(const uint4*)(srcBl + nb);
        uint4 vbl1 = *(const uint4*)(srcBl + nb + 8);
        __syncthreads();
        *(uint4*)(__cvta_shared_to_generic(dA_h))      = vah0;
        *(uint4*)(__cvta_shared_to_generic(dA_h + 16)) = vah1;
        *(uint4*)(__cvta_shared_to_generic(dA_l))      = val0;
        *(uint4*)(__cvta_shared_to_generic(dA_l + 16)) = val1;
        *(uint4*)(__cvta_shared_to_generic(dB_h))      = vbh0;
        *(uint4*)(__cvta_shared_to_generic(dB_h + 16)) = vbh1;
        *(uint4*)(__cvta_shared_to_generic(dB_l))      = vbl0;
        *(uint4*)(__cvta_shared_to_generic(dB_l + 16)) = vbl1;
        __syncthreads();
        #pragma unroll
        for (int kk = 0; kk < 2; kk++) {
            int kc = kk*16;
            uint32_t bh[8], bl[8];
            #pragma unroll
            for (int pair = 0; pair < 2; pair++) {
                unsigned off = (unsigned)(((brow + pair*16)*OSTR + bcol + kc) * 2);
                ldmx4(bh + pair*4, aBh + off);
                ldmx4(bl + pair*4, aBl + off);
            }
            #pragma unroll
            for (int ct = 0; ct < 4; ct++) {
                unsigned off = (unsigned)(((arow + ct*16)*OSTR + acol + kc) * 2);
                uint32_t ah[4], al[4];
                ldmx4(ah, aAh + off);
                ldmx4(al, aAl + off);
                #pragma unroll
                for (int mt = 0; mt < 4; mt++) {
                    const uint32_t* pbh = bh + (mt >> 1)*4 + (mt & 1)*2;
                    const uint32_t* pbl = bl + (mt >> 1)*4 + (mt & 1)*2;
                    mma16816(acc[ct][mt], ah, pbh);
                    mma16816(acc[ct][mt], ah, pbl);
                    mma16816(acc[ct][mt], al, pbh);
                }
            }
        }
    }

    // epilogue: out = acc + x1 * (1 + cw)
    int colb = 2*(lane & 3);
    #pragma unroll
    for (int ct = 0; ct < 4; ct++) {
        int cb = c0 + wc*64 + ct*16 + (lane >> 2);
        float cw0 = 1.f + g_cw[b*C1_ + cb];
        float cw1 = 1.f + g_cw[b*C1_ + cb + 8];
        #pragma unroll
        for (int mt = 0; mt < 4; mt++) {
            int m = m0 + wm*32 + mt*8 + colb;
            size_t o0 = ((size_t)(b*C1_ + cb))*N1_ + m;
            size_t o1 = ((size_t)(b*C1_ + cb + 8))*N1_ + m;
            float2 x0 = *(const float2*)(x1 + o0);
            float2 x1v = *(const float2*)(x1 + o1);
            *(float2*)(out + o0) = make_float2(fmaf(x0.x, cw0, acc[ct][mt][0]),
                                               fmaf(x0.y, cw0, acc[ct][mt][1]));
            *(float2*)(out + o1) = make_float2(fmaf(x1v.x, cw1, acc[ct][mt][2]),
                                               fmaf(x1v.y, cw1, acc[ct][mt][3]));
        }
    }
}

// ---------------- channel branch: cf logits (1x1 conv) --------------------
__global__ __launch_bounds__(256) void cf_logit_k(const float* __restrict__ x1,
                                                  const float* __restrict__ wc)
{
    __shared__ float wc_s[C1_];
    int t = threadIdx.x, b = blockIdx.y;
    wc_s[t] = wc[t];
    __syncthreads();
    int n = blockIdx.x*256 + t;
    const float* xp = x1 + (size_t)b*C1_*N1_ + n;
    float s0 = 0.f, s1 = 0.f, s2 = 0.f, s3 = 0.f;
    #pragma unroll 4
    for (int c = 0; c < C1_; c += 4) {
        s0 = fmaf(wc_s[c+0], __ldg(xp + (size_t)(c+0)*N1_), s0);
        s1 = fmaf(wc_s[c+1], __ldg(xp + (size_t)(c+1)*N1_), s1);
        s2 = fmaf(wc_s[c+2], __ldg(xp + (size_t)(c+2)*N1_), s2);
        s3 = fmaf(wc_s[c+3], __ldg(xp + (size_t)(c+3)*N1_), s3);
    }
    g_logit[b*N1_ + n] = (s0 + s1) + (s2 + s3);
}

// ---------------- cf softmax over N1 (per b) -------------------------------
__global__ __launch_bounds__(1024) void cf_softmax_k()
{
    int b = blockIdx.x, t = threadIdx.x;
    __shared__ float red[32];
    float v[4];
    #pragma unroll
    for (int i = 0; i < 4; i++) v[i] = g_logit[b*N1_ + t + 1024*i];
    float mx = fmaxf(fmaxf(v[0],v[1]), fmaxf(v[2],v[3]));
    #pragma unroll
    for (int o = 16; o; o >>= 1) mx = fmaxf(mx, __shfl_xor_sync(~0u, mx, o));
    if ((t&31) == 0) red[t>>5] = mx;
    __syncthreads();
    if (t < 32) {
        float m2 = red[t];
        #pragma unroll
        for (int o = 16; o; o >>= 1) m2 = fmaxf(m2, __shfl_xor_sync(~0u, m2, o));
        red[t] = m2;
    }
    __syncthreads();
    mx = red[0];
    __syncthreads();
    float e[4]; float s = 0.f;
    #pragma unroll
    for (int i = 0; i < 4; i++) { e[i] = fexp(v[i]-mx); s += e[i]; }
    #pragma unroll
    for (int o = 16; o; o >>= 1) s += __shfl_xor_sync(~0u, s, o);
    if ((t&31) == 0) red[t>>5] = s;
    __syncthreads();
    if (t < 32) {
        float s2 = red[t];
        #pragma unroll
        for (int o = 16; o; o >>= 1) s2 += __shfl_xor_sync(~0u, s2, o);
        red[t] = s2;
    }
    __syncthreads();
    float inv = 1.f / red[0];
    #pragma unroll
    for (int i = 0; i < 4; i++) g_cf[b*N1_ + t + 1024*i] = e[i]*inv;
}

// ---------------- y[b,i,dy,dx] = sum_p x1[b,i,p]*cf_pad[b, p-(dy-1,dx-1)] --
__global__ __launch_bounds__(256) void y_k(const float* __restrict__ x1)
{
    __shared__ float cf_s[N1_];
    __shared__ float part[8][9];
    int i = blockIdx.x, b = blockIdx.y, t = threadIdx.x;
    for (int idx = t; idx < N1_; idx += 256) cf_s[idx] = g_cf[b*N1_ + idx];
    __syncthreads();
    float a[9];
    #pragma unroll
    for (int k = 0; k < 9; k++) a[k] = 0.f;
    const float* xp = x1 + ((size_t)(b*C1_ + i))*N1_;
    for (int p = t; p < N1_; p += 256) {
        float xv = xp[p];
        int ph = p >> 6, pw = p & 63;
        #pragma unroll
        for (int dy = 0; dy < 3; dy++) {
            int qh = ph + 1 - dy;
            if ((unsigned)qh < 64u) {
                #pragma unroll
                for (int dx = 0; dx < 3; dx++) {
                    int qw = pw + 1 - dx;
                    if ((unsigned)qw < 64u)
                        a[dy*3+dx] = fmaf(xv, cf_s[(qh<<6)+qw], a[dy*3+dx]);
                }
            }
        }
    }
    #pragma unroll
    for (int k = 0; k < 9; k++) {
        float s = a[k];
        #pragma unroll
        for (int o = 16; o; o >>= 1) s += __shfl_xor_sync(~0u, s, o);
        if ((t&31) == 0) part[t>>5][k] = s;
    }
    __syncthreads();
    if (t < 9) {
        float s = 0.f;
        #pragma unroll
        for (int w = 0; w < 8; w++) s += part[w][t];
        g_y[(b*C1_+i)*9 + t] = s;
    }
}

// ---------------- pool = wch*y ; t = wt1*pool ; LN ; relu ; cw = wt2*t -----
__global__ __launch_bounds__(256) void chtail_k(
    const float* __restrict__ wch, const float* __restrict__ wt1,
    const float* __restrict__ bt1, const float* __restrict__ lng,
    const float* __restrict__ lnb, const float* __restrict__ wt2,
    const float* __restrict__ bt2)
{
    __shared__ float y_s[C1_*9];
    __shared__ float pool_s[C1_];
    __shared__ float t_s[CR_];
    int b = blockIdx.x, t = threadIdx.x;
    for (int idx = t; idx < C1_*9; idx += 256) y_s[idx] = g_y[b*C1_*9 + idx];
    __syncthreads();
    {
        float a = 0.f;
        const float* wp = wch + (size_t)t*(C1_*9);
        #pragma unroll 4
        for (int idx = 0; idx < C1_*9; idx++) a = fmaf(wp[idx], y_s[idx], a);
        pool_s[t] = a;
    }
    __syncthreads();
    if (t < CR_) {
        float tv = bt1[t];
        const float* wp = wt1 + t*C1_;
        #pragma unroll 4
        for (int c = 0; c < C1_; c++) tv = fmaf(wp[c], pool_s[c], tv);
        float s1 = tv;
        #pragma unroll
        for (int o = 16; o; o >>= 1) s1 += __shfl_xor_sync(~0u, s1, o);
        float mu = s1 * (1.f/32.f);
        float d  = tv - mu;
        float s2 = d*d;
        #pragma unroll
        for (int o = 16; o; o >>= 1) s2 += __shfl_xor_sync(~0u, s2, o);
        float var = s2 * (1.f/32.f);
        float val = d * rsqrtf(var + 1e-5f) * lng[t] + lnb[t];
        t_s[t] = fmaxf(val, 0.f);
    }
    __syncthreads();
    {
        float a = bt2[t];
        const float* wp = wt2 + t*CR_;
        #pragma unroll
        for (int j = 0; j < CR_; j++) a = fmaf(wp[j], t_s[j], a);
        g_cw[b*C1_ + t] = a;
    }
}

// ---------------------------------------------------------------------------
extern "C" void kernel_launch(void* const* d_in, const int* in_sizes, int n_in,
                              void* d_out, int out_size)
{
    (void)in_sizes; (void)n_in; (void)out_size;
    const float* x1  = (const float*)d_in[0];
    const float* x2  = (const float*)d_in[1];
    const float* wq  = (const float*)d_in[2];
    const float* wk  = (const float*)d_in[3];
    const float* wv  = (const float*)d_in[4];
    const float* wc  = (const float*)d_in[5];
    const float* wch = (const float*)d_in[6];
    const float* wt1 = (const float*)d_in[7];
    const float* bt1 = (const float*)d_in[8];
    const float* lng = (const float*)d_in[9];
    const float* lnb = (const float*)d_in[10];
    const float* wt2 = (const float*)d_in[11];
    const float* bt2 = (const float*)d_in[12];
    float* out = (float*)d_out;

    float *pq, *pqp, *pk, *pkp, *pv, *pvp;
    cudaGetSymbolAddress((void**)&pq,  g_q);
    cudaGetSymbolAddress((void**)&pqp, g_qpart);
    cudaGetSymbolAddress((void**)&pk,  g_k);
    cudaGetSymbolAddress((void**)&pkp, g_kpart);
    cudaGetSymbolAddress((void**)&pv,  g_v);
    cudaGetSymbolAddress((void**)&pvp, g_vpart);

    // conv_v: Cin 512 split 4x128, Cout 256 in 4 blocks of 64 (COPT=8)
    conv3x3_t<8,2><<<dim3(4, 16, B_), 256>>>(x2, wv, pvp, C2_, 128, C1_,
                                             H2_, W2_, 2, 4, (long)B_*C1_*N2_);
    reduce_slabs<<<2048, 256>>>((const float4*)pvp, (float4*)pv, 4, B_*C1_*N2_/4);
    vconv_k<<<B_*C1_*N2_/(4*256), 256>>>();

    // conv_q: Cin 256 split 4x64, Cout 32 (COPT=4)
    conv3x3_t<4,3><<<dim3(16, 4, B_), 256>>>(x1, wq, pqp, C1_, 64, CR_,
                                             H1_, W1_, 4, 1, (long)B_*CR_*N1_);
    reduce_slabs<<<1024, 256>>>((const float4*)pqp, (float4*)pq, 4, B_*CR_*N1_/4);

    // conv_k: Cin 512 split 8x64, Cout 32 (COPT=4)
    conv3x3_t<4,3><<<dim3(4, 8, B_), 256>>>(x2, wk, pkp, C2_, 64, CR_,
                                            H2_, W2_, 2, 1, (long)B_*CR_*N2_);
    reduce_slabs<<<256, 256>>>((const float4*)pkp, (float4*)pk, 8, B_*CR_*N2_/4);

    // channel branch
    cf_logit_k<<<dim3(N1_/256, B_), 256>>>(x1, wc);
    cf_softmax_k<<<B_, 1024>>>();
    y_k<<<dim3(C1_, B_), 256>>>(x1);
    chtail_k<<<B_, 256>>>(wch, wt1, bt1, lng, lnb, wt2, bt2);

    // attention: S GEMM (f32x2) -> softmax (emit bf16 hi/lo) -> mma.sync O GEMM
    s_gemm_k<<<dim3(N1_/128, N2_/128, B_), 256>>>();
    softmax_k<<<dim3(N1_/8, B_), 256>>>();
    o_mma_k<<<dim3(N1_/128, C1_/128, B_), 256>>>(x1, out);
}

// round 10
// speedup vs baseline: 2.3122x; 1.3319x over previous
#include <cuda_runtime.h>
#include <cuda_bf16.h>
#include <cstdint>

#define B_ 8
#define C1_ 256
#define C2_ 512
#define H1_ 64
#define W1_ 64
#define N1_ 4096
#define H2_ 32
#define W2_ 32
#define N2_ 1024
#define CR_ 32
#define KQ_ (C1_*9)     // 2304
#define KV_ (C2_*9)     // 4608

typedef unsigned long long ull;

// ---------------- scratch (device globals; no allocations) ----------------
__device__ float g_q[B_*CR_*N1_];        // [b][c][m]
__device__ float g_k[B_*CR_*N2_];        // [b][c][n]
__device__ float g_S[B_*N1_*N2_];        // scores [b][m][n]
__device__ __nv_bfloat16 g_Ph[B_*N1_*N2_];  // P hi/lo split
__device__ __nv_bfloat16 g_Pl[B_*N1_*N2_];
__device__ __nv_bfloat16 g_vh[B_*C1_*N2_];  // V hi/lo split
__device__ __nv_bfloat16 g_vl[B_*C1_*N2_];
__device__ __nv_bfloat16 g_i2h1[(size_t)B_*KQ_*N1_];  // im2col(x1) hi/lo
__device__ __nv_bfloat16 g_i2l1[(size_t)B_*KQ_*N1_];
__device__ __nv_bfloat16 g_i2h2[(size_t)B_*KV_*N2_];  // im2col(x2) hi/lo
__device__ __nv_bfloat16 g_i2l2[(size_t)B_*KV_*N2_];
__device__ __nv_bfloat16 g_wvh[C1_*KV_], g_wvl[C1_*KV_];
__device__ __nv_bfloat16 g_wqh[CR_*KQ_], g_wql[CR_*KQ_];
__device__ __nv_bfloat16 g_wkh[CR_*KV_], g_wkl[CR_*KV_];
__device__ float g_logit[B_*N1_];
__device__ float g_cf[B_*N1_];
__device__ float g_y[B_*C1_*9];
__device__ float g_cw[B_*C1_];

// ---------------- f32x2 helpers -------------------------------------------
__device__ __forceinline__ ull pack2(float x, float y) {
    ull r;
    asm("mov.b64 %0, {%1, %2};" : "=l"(r) : "f"(x), "f"(y));
    return r;
}
__device__ __forceinline__ void unpack2(ull v, float& x, float& y) {
    asm("mov.b64 {%0, %1}, %2;" : "=f"(x), "=f"(y) : "l"(v));
}
__device__ __forceinline__ void ffma2(ull& d, ull a, ull b) {
    asm("fma.rn.f32x2 %0, %1, %2, %0;" : "+l"(d) : "l"(a), "l"(b));
}
__device__ __forceinline__ ull lds64(unsigned addr) {
    ull r;
    asm volatile("ld.shared.b64 %0, [%1];" : "=l"(r) : "r"(addr));
    return r;
}
__device__ __forceinline__ uint32_t smem_u32(const void* p) {
    uint32_t a;
    asm("{ .reg .u64 t; cvta.to.shared.u64 t, %1; cvt.u32.u64 %0, t; }"
        : "=r"(a) : "l"(p));
    return a;
}

// ---------------- mma.sync helpers ----------------------------------------
__device__ __forceinline__ void ldmx4(uint32_t* r, unsigned a) {
    asm volatile("ldmatrix.sync.aligned.m8n8.x4.shared.b16 {%0,%1,%2,%3}, [%4];"
        : "=r"(r[0]), "=r"(r[1]), "=r"(r[2]), "=r"(r[3]) : "r"(a));
}
__device__ __forceinline__ void ldmx4t(uint32_t* r, unsigned a) {
    asm volatile("ldmatrix.sync.aligned.m8n8.x4.trans.shared.b16 {%0,%1,%2,%3}, [%4];"
        : "=r"(r[0]), "=r"(r[1]), "=r"(r[2]), "=r"(r[3]) : "r"(a));
}
__device__ __forceinline__ void mma16816(float* d, const uint32_t* a,
                                         const uint32_t* b) {
    asm volatile(
        "mma.sync.aligned.m16n8k16.row.col.f32.bf16.bf16.f32 "
        "{%0,%1,%2,%3}, {%4,%5,%6,%7}, {%8,%9}, {%0,%1,%2,%3};"
        : "+f"(d[0]), "+f"(d[1]), "+f"(d[2]), "+f"(d[3])
        : "r"(a[0]), "r"(a[1]), "r"(a[2]), "r"(a[3]), "r"(b[0]), "r"(b[1]));
}
__device__ __forceinline__ void bf16split2(float v0, float v1,
                                           __nv_bfloat162& h, __nv_bfloat162& l) {
    h.x = __float2bfloat16_rn(v0); h.y = __float2bfloat16_rn(v1);
    l.x = __float2bfloat16_rn(v0 - __bfloat162float(h.x));
    l.y = __float2bfloat16_rn(v1 - __bfloat162float(h.y));
}

// ---------------- fast exp on FMA pipe ------------------------------------
__device__ __forceinline__ float fexp(float x) {
    x = fmaxf(x, -80.f);
    float t = x * 1.4426950408889634f;
    float z = t + 12582912.f;
    int   i = __float_as_int(z) - 0x4B400000;
    float f = t - (z - 12582912.f);
    float y = f * 0.6931471805599453f;
    float p = 1.f/720.f;
    p = fmaf(p, y, 1.f/120.f);
    p = fmaf(p, y, 1.f/24.f);
    p = fmaf(p, y, 1.f/6.f);
    p = fmaf(p, y, 0.5f);
    p = fmaf(p, y, 1.f);
    p = fmaf(p, y, 1.f);
    return p * __int_as_float((i + 127) << 23);
}

// ---------------- weight fp32 -> bf16 hi/lo -------------------------------
__global__ __launch_bounds__(256) void wsplit_k(const float* __restrict__ w,
                                                __nv_bfloat16* __restrict__ h,
                                                __nv_bfloat16* __restrict__ l,
                                                int n)
{
    int i = blockIdx.x*256 + threadIdx.x;
    if (i >= n) return;
    float v = w[i];
    __nv_bfloat16 hv = __float2bfloat16_rn(v);
    h[i] = hv;
    l[i] = __float2bfloat16_rn(v - __bfloat162float(hv));
}

// ---------------- im2col of x2 (32x32), k = ci*9 + dy*3+dx ----------------
__global__ __launch_bounds__(256) void im2col2_k(const float* __restrict__ x2)
{
    __shared__ float img[8*1024];
    int t = threadIdx.x, cig = blockIdx.x, b = blockIdx.y;
    const float* src = x2 + ((size_t)(b*C2_ + cig*8))*N2_;
    for (int i = t; i < 8*1024; i += 256) img[i] = src[i];
    __syncthreads();
    #pragma unroll
    for (int ci = 0; ci < 8; ci++) {
        size_t kbase = (size_t)b*KV_ + (size_t)(cig*8+ci)*9;
        #pragma unroll
        for (int j = 0; j < 9; j++) {
            int dy = j/3 - 1, dx = j%3 - 1;
            size_t dst = (kbase + j)*N2_;
            #pragma unroll
            for (int rep = 0; rep < 2; rep++) {
                int n = 2*(t + 256*rep);
                int h = n >> 5, w = n & 31;
                int sh = h + dy;
                float v0 = 0.f, v1 = 0.f;
                if ((unsigned)sh < 32u) {
                    int sw0 = w + dx;
                    if ((unsigned)sw0 < 32u) v0 = img[ci*1024 + (sh<<5) + sw0];
                    if ((unsigned)(sw0+1) < 32u) v1 = img[ci*1024 + (sh<<5) + sw0 + 1];
                }
                __nv_bfloat162 hh, ll;
                bf16split2(v0, v1, hh, ll);
                *(__nv_bfloat162*)(g_i2h2 + dst + n) = hh;
                *(__nv_bfloat162*)(g_i2l2 + dst + n) = ll;
            }
        }
    }
}

// ---------------- im2col of x1 (64x64) ------------------------------------
__global__ __launch_bounds__(256) void im2col1_k(const float* __restrict__ x1)
{
    __shared__ float img[4096];
    int t = threadIdx.x, ci = blockIdx.x, b = blockIdx.y;
    const float* src = x1 + ((size_t)(b*C1_ + ci))*N1_;
    for (int i = t; i < 4096; i += 256) img[i] = src[i];
    __syncthreads();
    size_t kbase = (size_t)b*KQ_ + (size_t)ci*9;
    #pragma unroll
    for (int j = 0; j < 9; j++) {
        int dy = j/3 - 1, dx = j%3 - 1;
        size_t dst = (kbase + j)*N1_;
        #pragma unroll
        for (int rep = 0; rep < 8; rep++) {
            int n = 2*(t + 256*rep);
            int h = n >> 6, w = n & 63;
            int sh = h + dy;
            float v0 = 0.f, v1 = 0.f;
            if ((unsigned)sh < 64u) {
                int sw0 = w + dx;
                if ((unsigned)sw0 < 64u) v0 = img[(sh<<6) + sw0];
                if ((unsigned)(sw0+1) < 64u) v1 = img[(sh<<6) + sw0 + 1];
            }
            __nv_bfloat162 hh, ll;
            bf16split2(v0, v1, hh, ll);
            *(__nv_bfloat162*)(g_i2h1 + dst + n) = hh;
            *(__nv_bfloat162*)(g_i2l1 + dst + n) = ll;
        }
    }
}

// ---------------- conv_v as GEMM: D[256co][1024n] = W[co][k] I[k][n] ------
// tile 128x128, K=4608 in chunks of 32; hi/lo 3-product; emits g_vh/g_vl.
#define GV_AP 40
#define GV_BP 136
__global__ __launch_bounds__(256) void gemm_v_k()
{
    __shared__ __nv_bfloat16 Ah_s[128*GV_AP], Al_s[128*GV_AP];
    __shared__ __nv_bfloat16 Bh_s[32*GV_BP],  Bl_s[32*GV_BP];
    const int K = KV_;
    int t = threadIdx.x, b = blockIdx.z;
    int n0 = blockIdx.x*128, co0 = blockIdx.y*128;
    int lane = t & 31, wid = t >> 5;
    int wc = wid >> 2, wm = wid & 3;

    const __nv_bfloat16* Ih = g_i2h2 + (size_t)b*K*N2_;
    const __nv_bfloat16* Il = g_i2l2 + (size_t)b*K*N2_;
    int ar = t >> 2, ac = (t & 3) * 8;
    int br = t >> 4, bc = (t & 15) * 8;
    unsigned sAh = smem_u32(Ah_s), sAl = smem_u32(Al_s);
    unsigned sBh = smem_u32(Bh_s), sBl = smem_u32(Bl_s);

    float acc[4][4][4];
    #pragma unroll
    for (int i = 0; i < 4; i++)
        #pragma unroll
        for (int j = 0; j < 4; j++)
            #pragma unroll
            for (int k = 0; k < 4; k++) acc[i][j][k] = 0.f;

    for (int kb = 0; kb < K; kb += 32) {
        uint4 vah0 = *(const uint4*)(g_wvh + (size_t)(co0+ar)*K + kb + ac);
        uint4 vah1 = *(const uint4*)(g_wvh + (size_t)(co0+ar+64)*K + kb + ac);
        uint4 val0 = *(const uint4*)(g_wvl + (size_t)(co0+ar)*K + kb + ac);
        uint4 val1 = *(const uint4*)(g_wvl + (size_t)(co0+ar+64)*K + kb + ac);
        uint4 vbh0 = *(const uint4*)(Ih + (size_t)(kb+br)*N2_ + n0 + bc);
        uint4 vbh1 = *(const uint4*)(Ih + (size_t)(kb+br+16)*N2_ + n0 + bc);
        uint4 vbl0 = *(const uint4*)(Il + (size_t)(kb+br)*N2_ + n0 + bc);
        uint4 vbl1 = *(const uint4*)(Il + (size_t)(kb+br+16)*N2_ + n0 + bc);
        __syncthreads();
        *(uint4*)(Ah_s + ar*GV_AP + ac)      = vah0;
        *(uint4*)(Ah_s + (ar+64)*GV_AP + ac) = vah1;
        *(uint4*)(Al_s + ar*GV_AP + ac)      = val0;
        *(uint4*)(Al_s + (ar+64)*GV_AP + ac) = val1;
        *(uint4*)(Bh_s + br*GV_BP + bc)      = vbh0;
        *(uint4*)(Bh_s + (br+16)*GV_BP + bc) = vbh1;
        *(uint4*)(Bl_s + br*GV_BP + bc)      = vbl0;
        *(uint4*)(Bl_s + (br+16)*GV_BP + bc) = vbl1;
        __syncthreads();
        #pragma unroll
        for (int kk = 0; kk < 2; kk++) {
            uint32_t bh[2][4], bl[2][4];
            #pragma unroll
            for (int p = 0; p < 2; p++) {
                unsigned off = (unsigned)(((kk*16 + (lane&15))*GV_BP
                               + wm*32 + p*16 + 8*(lane>>4)) * 2);
                ldmx4t(bh[p], sBh + off);
                ldmx4t(bl[p], sBl + off);
            }
            #pragma unroll
            for (int ct = 0; ct < 4; ct++) {
                unsigned off = (unsigned)(((wc*64 + ct*16 + (lane&15))*GV_AP
                               + kk*16 + 8*(lane>>4)) * 2);
                uint32_t ah[4], al[4];
                ldmx4(ah, sAh + off);
                ldmx4(al, sAl + off);
                #pragma unroll
                for (int mt = 0; mt < 4; mt++) {
                    const uint32_t* pbh = bh[mt>>1] + (mt&1)*2;
                    const uint32_t* pbl = bl[mt>>1] + (mt&1)*2;
                    mma16816(acc[ct][mt], ah, pbh);
                    mma16816(acc[ct][mt], ah, pbl);
                    mma16816(acc[ct][mt], al, pbh);
                }
            }
        }
    }
    #pragma unroll
    for (int ct = 0; ct < 4; ct++) {
        int r0 = co0 + wc*64 + ct*16 + (lane>>2);
        #pragma unroll
        for (int mt = 0; mt < 4; mt++) {
            int col = n0 + wm*32 + mt*8 + 2*(lane&3);
            size_t o0 = ((size_t)(b*C1_) + r0)*N2_ + col;
            __nv_bfloat162 h, l;
            bf16split2(acc[ct][mt][0], acc[ct][mt][1], h, l);
            *(__nv_bfloat162*)(g_vh + o0) = h;
            *(__nv_bfloat162*)(g_vl + o0) = l;
            size_t o1 = o0 + (size_t)8*N2_;
            bf16split2(acc[ct][mt][2], acc[ct][mt][3], h, l);
            *(__nv_bfloat162*)(g_vh + o1) = h;
            *(__nv_bfloat162*)(g_vl + o1) = l;
        }
    }
}

// ---------------- conv_q / conv_k as GEMM: D[32co][Nn] --------------------
// tile 32x256, 8 n-warps, hi/lo 3-product; fp32 out.
#define GQ_AP 40
#define GQ_BP 264
__global__ __launch_bounds__(256) void gemm_qk_k(
    const __nv_bfloat16* __restrict__ Wh, const __nv_bfloat16* __restrict__ Wl,
    const __nv_bfloat16* __restrict__ I2h, const __nv_bfloat16* __restrict__ I2l,
    float* __restrict__ out, int K, int Ntot)
{
    __shared__ __nv_bfloat16 Ah_s[32*GQ_AP], Al_s[32*GQ_AP];
    __shared__ __nv_bfloat16 Bh_s[32*GQ_BP], Bl_s[32*GQ_BP];
    int t = threadIdx.x, b = blockIdx.z;
    int n0 = blockIdx.x*256;
    int lane = t & 31, wm = t >> 5;
    const __nv_bfloat16* Ih = I2h + (size_t)b*K*Ntot;
    const __nv_bfloat16* Il = I2l + (size_t)b*K*Ntot;
    int ar = t >> 2, ac = (t & 3)*8;
    bool doA = (t < 128);
    unsigned sAh = smem_u32(Ah_s), sAl = smem_u32(Al_s);
    unsigned sBh = smem_u32(Bh_s), sBl = smem_u32(Bl_s);

    float acc[2][4][4];
    #pragma unroll
    for (int i = 0; i < 2; i++)
        #pragma unroll
        for (int j = 0; j < 4; j++)
            #pragma unroll
            for (int k = 0; k < 4; k++) acc[i][j][k] = 0.f;

    for (int kb = 0; kb < K; kb += 32) {
        uint4 sa_h, sa_l;
        if (doA) {
            sa_h = *(const uint4*)(Wh + (size_t)ar*K + kb + ac);
            sa_l = *(const uint4*)(Wl + (size_t)ar*K + kb + ac);
        }
        uint4 vbh[4], vbl[4];
        #pragma unroll
        for (int j = 0; j < 4; j++) {
            int i = t + 256*j;
            int r = i >> 5, c8 = (i & 31)*8;
            vbh[j] = *(const uint4*)(Ih + (size_t)(kb+r)*Ntot + n0 + c8);
            vbl[j] = *(const uint4*)(Il + (size_t)(kb+r)*Ntot + n0 + c8);
        }
        __syncthreads();
        if (doA) {
            *(uint4*)(Ah_s + ar*GQ_AP + ac) = sa_h;
            *(uint4*)(Al_s + ar*GQ_AP + ac) = sa_l;
        }
        #pragma unroll
        for (int j = 0; j < 4; j++) {
            int i = t + 256*j;
            int r = i >> 5, c8 = (i & 31)*8;
            *(uint4*)(Bh_s + r*GQ_BP + c8) = vbh[j];
            *(uint4*)(Bl_s + r*GQ_BP + c8) = vbl[j];
        }
        __syncthreads();
        #pragma unroll
        for (int kk = 0; kk < 2; kk++) {
            uint32_t bh[2][4], bl[2][4];
            #pragma unroll
            for (int p = 0; p < 2; p++) {
                unsigned off = (unsigned)(((kk*16 + (lane&15))*GQ_BP
                               + wm*32 + p*16 + 8*(lane>>4)) * 2);
                ldmx4t(bh[p], sBh + off);
                ldmx4t(bl[p], sBl + off);
            }
            #pragma unroll
            for (int ct = 0; ct < 2; ct++) {
                unsigned off = (unsigned)(((ct*16 + (lane&15))*GQ_AP
                               + kk*16 + 8*(lane>>4)) * 2);
                uint32_t ah[4], al[4];
                ldmx4(ah, sAh + off);
                ldmx4(al, sAl + off);
                #pragma unroll
                for (int mt = 0; mt < 4; mt++) {
                    const uint32_t* pbh = bh[mt>>1] + (mt&1)*2;
                    const uint32_t* pbl = bl[mt>>1] + (mt&1)*2;
                    mma16816(acc[ct][mt], ah, pbh);
                    mma16816(acc[ct][mt], ah, pbl);
                    mma16816(acc[ct][mt], al, pbh);
                }
            }
        }
    }
    #pragma unroll
    for (int ct = 0; ct < 2; ct++) {
        int r0 = ct*16 + (lane>>2);
        #pragma unroll
        for (int mt = 0; mt < 4; mt++) {
            int col = n0 + wm*32 + mt*8 + 2*(lane&3);
            size_t o0 = ((size_t)(b*CR_) + r0)*Ntot + col;
            *(float2*)(out + o0) = make_float2(acc[ct][mt][0], acc[ct][mt][1]);
            size_t o1 = o0 + (size_t)8*Ntot;
            *(float2*)(out + o1) = make_float2(acc[ct][mt][2], acc[ct][mt][3]);
        }
    }
}

// ---------------- S[m][n] = sum_c q[c][m] k[c][n]  (128x128 tiles) --------
__global__ __launch_bounds__(256, 2) void s_gemm_k()
{
    __shared__ float q_s[32*128];
    __shared__ float k_s[32*128];
    int t = threadIdx.x, b = blockIdx.z;
    int m0 = blockIdx.x*128, n0 = blockIdx.y*128;
    for (int i = t; i < 1024; i += 256) {
        int c = i >> 5, j = i & 31;
        ((float4*)q_s)[i] = *(const float4*)(g_q + ((size_t)(b*CR_ + c))*N1_ + m0 + 4*j);
        ((float4*)k_s)[i] = *(const float4*)(g_k + ((size_t)(b*CR_ + c))*N2_ + n0 + 4*j);
    }
    __syncthreads();
    int tn = t & 15, tm = t >> 4;
    unsigned kb = (unsigned)__cvta_generic_to_shared(k_s);
    ull acc2[8][4];
    #pragma unroll
    for (int im = 0; im < 8; im++)
        #pragma unroll
        for (int jn = 0; jn < 4; jn++) acc2[im][jn] = 0ull;
    #pragma unroll 4
    for (int c = 0; c < 32; c++) {
        ull ad[8], bd[4];
        #pragma unroll
        for (int im = 0; im < 8; im++) {
            float qv = q_s[c*128 + tm*8 + im];
            ad[im] = pack2(qv, qv);
        }
        #pragma unroll
        for (int jn = 0; jn < 4; jn++)
            bd[jn] = lds64(kb + (unsigned)((c*128 + tn*2 + 32*jn) << 2));
        #pragma unroll
        for (int im = 0; im < 8; im++)
            #pragma unroll
            for (int jn = 0; jn < 4; jn++)
                ffma2(acc2[im][jn], ad[im], bd[jn]);
    }
    #pragma unroll
    for (int im = 0; im < 8; im++) {
        float* row = g_S + ((size_t)(b*N1_) + m0 + tm*8 + im)*N2_ + n0;
        #pragma unroll
        for (int jn = 0; jn < 4; jn++) {
            float x, y; unpack2(acc2[im][jn], x, y);
            *(float2*)(row + tn*2 + 32*jn) = make_float2(x, y);
        }
    }
}

// ---------------- row softmax over n; emit P as bf16 hi/lo ----------------
__global__ __launch_bounds__(256) void softmax_k()
{
    int b = blockIdx.y;
    int m = blockIdx.x*8 + (threadIdx.x >> 5);
    int lane = threadIdx.x & 31;
    size_t base = ((size_t)(b*N1_) + m)*N2_;
    const float4* row = (const float4*)(g_S + base);
    float4 v[8];
    #pragma unroll
    for (int j = 0; j < 8; j++) v[j] = row[lane + 32*j];
    float mx = -3e38f;
    #pragma unroll
    for (int j = 0; j < 8; j++)
        mx = fmaxf(mx, fmaxf(fmaxf(v[j].x, v[j].y), fmaxf(v[j].z, v[j].w)));
    #pragma unroll
    for (int o = 16; o; o >>= 1) mx = fmaxf(mx, __shfl_xor_sync(~0u, mx, o));
    float s = 0.f;
    #pragma unroll
    for (int j = 0; j < 8; j++) {
        v[j].x = fexp(v[j].x - mx); v[j].y = fexp(v[j].y - mx);
        v[j].z = fexp(v[j].z - mx); v[j].w = fexp(v[j].w - mx);
        s += v[j].x + v[j].y + v[j].z + v[j].w;
    }
    #pragma unroll
    for (int o = 16; o; o >>= 1) s += __shfl_xor_sync(~0u, s, o);
    float inv = 1.f / s;
    __nv_bfloat162* ph = (__nv_bfloat162*)(g_Ph + base);
    __nv_bfloat162* pl = (__nv_bfloat162*)(g_Pl + base);
    #pragma unroll
    for (int j = 0; j < 8; j++) {
        __nv_bfloat162 h0, h1, l0, l1;
        bf16split2(v[j].x*inv, v[j].y*inv, h0, l0);
        bf16split2(v[j].z*inv, v[j].w*inv, h1, l1);
        int q = lane + 32*j;
        ph[2*q] = h0; ph[2*q+1] = h1;
        pl[2*q] = l0; pl[2*q+1] = l1;
    }
}

// ---------------- mma.sync O-GEMM: O[c][m] = sum_n V[c][n] P[m][n] --------
#define OSTR 40
__global__ __launch_bounds__(256) void o_mma_k(const float* __restrict__ x1,
                                               float* __restrict__ out)
{
    __shared__ __nv_bfloat16 Ah_s[128*OSTR], Al_s[128*OSTR];
    __shared__ __nv_bfloat16 Bh_s[128*OSTR], Bl_s[128*OSTR];
    int t = threadIdx.x, b = blockIdx.z;
    int m0 = blockIdx.x*128, c0 = blockIdx.y*128;
    int lane = t & 31, wid = t >> 5;
    int wc = wid >> 2, wm = wid & 3;
    int r = t >> 1, half = t & 1;

    const __nv_bfloat16* srcAh = g_vh + ((size_t)(b*C1_ + c0 + r))*N2_ + half*16;
    const __nv_bfloat16* srcAl = g_vl + ((size_t)(b*C1_ + c0 + r))*N2_ + half*16;
    const __nv_bfloat16* srcBh = g_Ph + ((size_t)(b*N1_ + m0 + r))*N2_ + half*16;
    const __nv_bfloat16* srcBl = g_Pl + ((size_t)(b*N1_ + m0 + r))*N2_ + half*16;
    unsigned dA_h = smem_u32(Ah_s) + (unsigned)((r*OSTR + half*16) * 2);
    unsigned dA_l = smem_u32(Al_s) + (unsigned)((r*OSTR + half*16) * 2);
    unsigned dB_h = smem_u32(Bh_s) + (unsigned)((r*OSTR + half*16) * 2);
    unsigned dB_l = smem_u32(Bl_s) + (unsigned)((r*OSTR + half*16) * 2);

    unsigned aAh = smem_u32(Ah_s), aAl = smem_u32(Al_s);
    unsigned aBh = smem_u32(Bh_s), aBl = smem_u32(Bl_s);
    int arow = wc*64 + (lane & 15);
    int acol = (lane >> 4) * 8;
    int brow = wm*32 + (lane & 7) + ((lane >> 4) << 3);
    int bcol = ((lane >> 3) & 1) * 8;

    float acc[4][4][4];
    #pragma unroll
    for (int i = 0; i < 4; i++)
        #pragma unroll
        for (int j = 0; j < 4; j++)
            #pragma unroll
            for (int k = 0; k < 4; k++) acc[i][j][k] = 0.f;

    for (int nb = 0; nb < N2_; nb += 32) {
        uint4 vah0 = *(const uint4*)(srcAh + nb);
        uint4 vah1 = *(const uint4*)(srcAh + nb + 8);
        uint4 val0 = *(const uint4*)(srcAl + nb);
        uint4 val1 = *(const uint4*)(srcAl + nb + 8);
        uint4 vbh0 = *(const uint4*)(srcBh + nb);
        uint4 vbh1 = *(const uint4*)(srcBh + nb + 8);
        uint4 vbl0 = *(const uint4*)(srcBl + nb);
        uint4 vbl1 = *(const uint4*)(srcBl + nb + 8);
        __syncthreads();
        *(uint4*)(__cvta_shared_to_generic(dA_h))      = vah0;
        *(uint4*)(__cvta_shared_to_generic(dA_h + 16)) = vah1;
        *(uint4*)(__cvta_shared_to_generic(dA_l))      = val0;
        *(uint4*)(__cvta_shared_to_generic(dA_l + 16)) = val1;
        *(uint4*)(__cvta_shared_to_generic(dB_h))      = vbh0;
        *(uint4*)(__cvta_shared_to_generic(dB_h + 16)) = vbh1;
        *(uint4*)(__cvta_shared_to_generic(dB_l))      = vbl0;
        *(uint4*)(__cvta_shared_to_generic(dB_l + 16)) = vbl1;
        __syncthreads();
        #pragma unroll
        for (int kk = 0; kk < 2; kk++) {
            int kc = kk*16;
            uint32_t bh[8], bl[8];
            #pragma unroll
            for (int pair = 0; pair < 2; pair++) {
                unsigned off = (unsigned)(((brow + pair*16)*OSTR + bcol + kc) * 2);
                ldmx4(bh + pair*4, aBh + off);
                ldmx4(bl + pair*4, aBl + off);
            }
            #pragma unroll
            for (int ct = 0; ct < 4; ct++) {
                unsigned off = (unsigned)(((arow + ct*16)*OSTR + acol + kc) * 2);
                uint32_t ah[4], al[4];
                ldmx4(ah, aAh + off);
                ldmx4(al, aAl + off);
                #pragma unroll
                for (int mt = 0; mt < 4; mt++) {
                    const uint32_t* pbh = bh + (mt >> 1)*4 + (mt & 1)*2;
                    const uint32_t* pbl = bl + (mt >> 1)*4 + (mt & 1)*2;
                    mma16816(acc[ct][mt], ah, pbh);
                    mma16816(acc[ct][mt], ah, pbl);
                    mma16816(acc[ct][mt], al, pbh);
                }
            }
        }
    }

    int colb = 2*(lane & 3);
    #pragma unroll
    for (int ct = 0; ct < 4; ct++) {
        int cb = c0 + wc*64 + ct*16 + (lane >> 2);
        float cw0 = 1.f + g_cw[b*C1_ + cb];
        float cw1 = 1.f + g_cw[b*C1_ + cb + 8];
        #pragma unroll
        for (int mt = 0; mt < 4; mt++) {
            int m = m0 + wm*32 + mt*8 + colb;
            size_t o0 = ((size_t)(b*C1_ + cb))*N1_ + m;
            size_t o1 = ((size_t)(b*C1_ + cb + 8))*N1_ + m;
            float2 x0 = *(const float2*)(x1 + o0);
            float2 x1v = *(const float2*)(x1 + o1);
            *(float2*)(out + o0) = make_float2(fmaf(x0.x, cw0, acc[ct][mt][0]),
                                               fmaf(x0.y, cw0, acc[ct][mt][1]));
            *(float2*)(out + o1) = make_float2(fmaf(x1v.x, cw1, acc[ct][mt][2]),
                                               fmaf(x1v.y, cw1, acc[ct][mt][3]));
        }
    }
}

// ---------------- channel branch: cf logits (1x1 conv) --------------------
__global__ __launch_bounds__(256) void cf_logit_k(const float* __restrict__ x1,
                                                  const float* __restrict__ wc)
{
    __shared__ float wc_s[C1_];
    int t = threadIdx.x, b = blockIdx.y;
    wc_s[t] = wc[t];
    __syncthreads();
    int n = blockIdx.x*256 + t;
    const float* xp = x1 + (size_t)b*C1_*N1_ + n;
    float s0 = 0.f, s1 = 0.f, s2 = 0.f, s3 = 0.f;
    #pragma unroll 4
    for (int c = 0; c < C1_; c += 4) {
        s0 = fmaf(wc_s[c+0], __ldg(xp + (size_t)(c+0)*N1_), s0);
        s1 = fmaf(wc_s[c+1], __ldg(xp + (size_t)(c+1)*N1_), s1);
        s2 = fmaf(wc_s[c+2], __ldg(xp + (size_t)(c+2)*N1_), s2);
        s3 = fmaf(wc_s[c+3], __ldg(xp + (size_t)(c+3)*N1_), s3);
    }
    g_logit[b*N1_ + n] = (s0 + s1) + (s2 + s3);
}

// ---------------- cf softmax over N1 (per b) -------------------------------
__global__ __launch_bounds__(1024) void cf_softmax_k()
{
    int b = blockIdx.x, t = threadIdx.x;
    __shared__ float red[32];
    float v[4];
    #pragma unroll
    for (int i = 0; i < 4; i++) v[i] = g_logit[b*N1_ + t + 1024*i];
    float mx = fmaxf(fmaxf(v[0],v[1]), fmaxf(v[2],v[3]));
    #pragma unroll
    for (int o = 16; o; o >>= 1) mx = fmaxf(mx, __shfl_xor_sync(~0u, mx, o));
    if ((t&31) == 0) red[t>>5] = mx;
    __syncthreads();
    if (t < 32) {
        float m2 = red[t];
        #pragma unroll
        for (int o = 16; o; o >>= 1) m2 = fmaxf(m2, __shfl_xor_sync(~0u, m2, o));
        red[t] = m2;
    }
    __syncthreads();
    mx = red[0];
    __syncthreads();
    float e[4]; float s = 0.f;
    #pragma unroll
    for (int i = 0; i < 4; i++) { e[i] = fexp(v[i]-mx); s += e[i]; }
    #pragma unroll
    for (int o = 16; o; o >>= 1) s += __shfl_xor_sync(~0u, s, o);
    if ((t&31) == 0) red[t>>5] = s;
    __syncthreads();
    if (t < 32) {
        float s2 = red[t];
        #pragma unroll
        for (int o = 16; o; o >>= 1) s2 += __shfl_xor_sync(~0u, s2, o);
        red[t] = s2;
    }
    __syncthreads();
    float inv = 1.f / red[0];
    #pragma unroll
    for (int i = 0; i < 4; i++) g_cf[b*N1_ + t + 1024*i] = e[i]*inv;
}

// ---------------- y[b,i,dy,dx] = sum_p x1[b,i,p]*cf_pad[b, p-(dy-1,dx-1)] --
__global__ __launch_bounds__(256) void y_k(const float* __restrict__ x1)
{
    __shared__ float cf_s[N1_];
    __shared__ float part[8][9];
    int i = blockIdx.x, b = blockIdx.y, t = threadIdx.x;
    for (int idx = t; idx < N1_; idx += 256) cf_s[idx] = g_cf[b*N1_ + idx];
    __syncthreads();
    float a[9];
    #pragma unroll
    for (int k = 0; k < 9; k++) a[k] = 0.f;
    const float* xp = x1 + ((size_t)(b*C1_ + i))*N1_;
    for (int p = t; p < N1_; p += 256) {
        float xv = xp[p];
        int ph = p >> 6, pw = p & 63;
        #pragma unroll
        for (int dy = 0; dy < 3; dy++) {
            int qh = ph + 1 - dy;
            if ((unsigned)qh < 64u) {
                #pragma unroll
                for (int dx = 0; dx < 3; dx++) {
                    int qw = pw + 1 - dx;
                    if ((unsigned)qw < 64u)
                        a[dy*3+dx] = fmaf(xv, cf_s[(qh<<6)+qw], a[dy*3+dx]);
                }
            }
        }
    }
    #pragma unroll
    for (int k = 0; k < 9; k++) {
        float s = a[k];
        #pragma unroll
        for (int o = 16; o; o >>= 1) s += __shfl_xor_sync(~0u, s, o);
        if ((t&31) == 0) part[t>>5][k] = s;
    }
    __syncthreads();
    if (t < 9) {
        float s = 0.f;
        #pragma unroll
        for (int w = 0; w < 8; w++) s += part[w][t];
        g_y[(b*C1_+i)*9 + t] = s;
    }
}

// ---------------- pool = wch*y ; t = wt1*pool ; LN ; relu ; cw = wt2*t -----
__global__ __launch_bounds__(256) void chtail_k(
    const float* __restrict__ wch, const float* __restrict__ wt1,
    const float* __restrict__ bt1, const float* __restrict__ lng,
    const float* __restrict__ lnb, const float* __restrict__ wt2,
    const float* __restrict__ bt2)
{
    __shared__ float y_s[C1_*9];
    __shared__ float pool_s[C1_];
    __shared__ float t_s[CR_];
    int b = blockIdx.x, t = threadIdx.x;
    for (int idx = t; idx < C1_*9; idx += 256) y_s[idx] = g_y[b*C1_*9 + idx];
    __syncthreads();
    {
        float a = 0.f;
        const float* wp = wch + (size_t)t*(C1_*9);
        #pragma unroll 4
        for (int idx = 0; idx < C1_*9; idx++) a = fmaf(wp[idx], y_s[idx], a);
        pool_s[t] = a;
    }
    __syncthreads();
    if (t < CR_) {
        float tv = bt1[t];
        const float* wp = wt1 + t*C1_;
        #pragma unroll 4
        for (int c = 0; c < C1_; c++) tv = fmaf(wp[c], pool_s[c], tv);
        float s1 = tv;
        #pragma unroll
        for (int o = 16; o; o >>= 1) s1 += __shfl_xor_sync(~0u, s1, o);
        float mu = s1 * (1.f/32.f);
        float d  = tv - mu;
        float s2 = d*d;
        #pragma unroll
        for (int o = 16; o; o >>= 1) s2 += __shfl_xor_sync(~0u, s2, o);
        float var = s2 * (1.f/32.f);
        float val = d * rsqrtf(var + 1e-5f) * lng[t] + lnb[t];
        t_s[t] = fmaxf(val, 0.f);
    }
    __syncthreads();
    {
        float a = bt2[t];
        const float* wp = wt2 + t*CR_;
        #pragma unroll
        for (int j = 0; j < CR_; j++) a = fmaf(wp[j], t_s[j], a);
        g_cw[b*C1_ + t] = a;
    }
}

// ---------------------------------------------------------------------------
extern "C" void kernel_launch(void* const* d_in, const int* in_sizes, int n_in,
                              void* d_out, int out_size)
{
    (void)in_sizes; (void)n_in; (void)out_size;
    const float* x1  = (const float*)d_in[0];
    const float* x2  = (const float*)d_in[1];
    const float* wq  = (const float*)d_in[2];
    const float* wk  = (const float*)d_in[3];
    const float* wv  = (const float*)d_in[4];
    const float* wc  = (const float*)d_in[5];
    const float* wch = (const float*)d_in[6];
    const float* wt1 = (const float*)d_in[7];
    const float* bt1 = (const float*)d_in[8];
    const float* lng = (const float*)d_in[9];
    const float* lnb = (const float*)d_in[10];
    const float* wt2 = (const float*)d_in[11];
    const float* bt2 = (const float*)d_in[12];
    float* out = (float*)d_out;

    float *pq, *pk;
    __nv_bfloat16 *pwvh, *pwvl, *pwqh, *pwql, *pwkh, *pwkl;
    __nv_bfloat16 *pi2h1, *pi2l1, *pi2h2, *pi2l2;
    cudaGetSymbolAddress((void**)&pq,    g_q);
    cudaGetSymbolAddress((void**)&pk,    g_k);
    cudaGetSymbolAddress((void**)&pwvh,  g_wvh);
    cudaGetSymbolAddress((void**)&pwvl,  g_wvl);
    cudaGetSymbolAddress((void**)&pwqh,  g_wqh);
    cudaGetSymbolAddress((void**)&pwql,  g_wql);
    cudaGetSymbolAddress((void**)&pwkh,  g_wkh);
    cudaGetSymbolAddress((void**)&pwkl,  g_wkl);
    cudaGetSymbolAddress((void**)&pi2h1, g_i2h1);
    cudaGetSymbolAddress((void**)&pi2l1, g_i2l1);
    cudaGetSymbolAddress((void**)&pi2h2, g_i2h2);
    cudaGetSymbolAddress((void**)&pi2l2, g_i2l2);

    // im2col + weight splits
    im2col2_k<<<dim3(C2_/8, B_), 256>>>(x2);
    im2col1_k<<<dim3(C1_, B_), 256>>>(x1);
    wsplit_k<<<(C1_*KV_ + 255)/256, 256>>>(wv, pwvh, pwvl, C1_*KV_);
    wsplit_k<<<(CR_*KQ_ + 255)/256, 256>>>(wq, pwqh, pwql, CR_*KQ_);
    wsplit_k<<<(CR_*KV_ + 255)/256, 256>>>(wk, pwkh, pwkl, CR_*KV_);

    // convs as tensor-core GEMMs
    gemm_v_k<<<dim3(N2_/128, C1_/128, B_), 256>>>();
    gemm_qk_k<<<dim3(N1_/256, 1, B_), 256>>>(pwqh, pwql, pi2h1, pi2l1, pq,
                                             KQ_, N1_);
    gemm_qk_k<<<dim3(N2_/256, 1, B_), 256>>>(pwkh, pwkl, pi2h2, pi2l2, pk,
                                             KV_, N2_);

    // channel branch
    cf_logit_k<<<dim3(N1_/256, B_), 256>>>(x1, wc);
    cf_softmax_k<<<B_, 1024>>>();
    y_k<<<dim3(C1_, B_), 256>>>(x1);
    chtail_k<<<B_, 256>>>(wch, wt1, bt1, lng, lnb, wt2, bt2);

    // attention: S GEMM (f32x2) -> softmax (bf16 hi/lo) -> mma.sync O GEMM
    s_gemm_k<<<dim3(N1_/128, N2_/128, B_), 256>>>();
    softmax_k<<<dim3(N1_/8, B_), 256>>>();
    o_mma_k<<<dim3(N1_/128, C1_/128, B_), 256>>>(x1, out);
}